// round 4
// baseline (speedup 1.0000x reference)
#include <cuda_runtime.h>
#include <cuda_fp16.h>
#include <math.h>
#include <stdint.h>

// ---------------------------------------------------------------------------
// RainbowNet fused inference — fp16 tensor-core + cp.async edition.
// Attention folded (cls query is batch-independent):
//   scores[h,j] = x_j . wscore_h + c_h ;  pooled = XW @ Mflat + c_pool
// All GEMMs: mma.sync.m16n8k16 f16 (fp32 accum), 3-stage cp.async pipeline.
// Weights pre-transposed to N-major fp16 each launch; activations fp16.
// ---------------------------------------------------------------------------

constexpr int BQ       = 8192;
constexpr int STATE_SZ = 1360;
constexpr int KPAD0    = 1504;   // 1488 padded to multiple of 32
constexpr int TRUNK_H  = 1024;
constexpr int HALF_H   = 512;
constexpr int ATOMS    = 51;
constexpr int ACTIONS  = 81;
constexpr int ADV_N    = ACTIONS * ATOMS;  // 4131

// byte offsets into g_bytes
constexpr size_t B_STATEH = 0;                       // 8192*1504 h
constexpr size_t B_XWH    = 24641536;                // 8192*512 h
constexpr size_t B_Z0     = 33030144;                // 8192*1024 f
constexpr size_t B_Z0H    = 66584576;                // 8192*1024 h
constexpr size_t B_H1     = 83361792;                // 8192*1024 f
constexpr size_t B_H1H    = 116916224;               // 8192*1024 h
constexpr size_t B_VALHH  = 133693440;               // 8192*512 h
constexpr size_t B_ADVHH  = 142082048;               // 8192*512 h
constexpr size_t B_VAL    = 150470656;               // 8192*51 f
constexpr size_t B_ADV    = 152141824;               // 8192*4131 f
constexpr size_t B_T0W    = 287506432;               // 1024*1504 h
constexpr size_t B_T1W    = 290586624;               // 1024*1024 h
constexpr size_t B_VFCW   = 292683776;               // 512*1024 h
constexpr size_t B_AFCW   = 293732352;               // 512*1024 h
constexpr size_t B_VOW    = 294780928;               // 51*512 h
constexpr size_t B_AOW    = 294833152;               // 4131*512 h
constexpr size_t B_MT     = 299063296;               // 128*512 h
constexpr size_t B_QVEC   = 299194368;               // 128 f
constexpr size_t B_WS     = 299194880;               // 512 f
constexpr size_t B_CS     = 299196928;               // 4 f (pad 64)
constexpr size_t B_CP     = 299196992;               // 128 f
constexpr size_t B_TOTAL  = 299197504;

__device__ __align__(256) unsigned char g_bytes[B_TOTAL];

__device__ __forceinline__ float wsum(float v) {
#pragma unroll
    for (int o = 16; o > 0; o >>= 1) v += __shfl_xor_sync(0xffffffffu, v, o);
    return v;
}
__device__ __forceinline__ float wmax(float v) {
#pragma unroll
    for (int o = 16; o > 0; o >>= 1) v = fmaxf(v, __shfl_xor_sync(0xffffffffu, v, o));
    return v;
}

// ---------------------------------------------------------------------------
// prep_small: qvec, wscore, cscore, cpool   (1 block, 128 threads)
// ---------------------------------------------------------------------------
__global__ void prep_small(const float* __restrict__ cls,
                           const float* __restrict__ ipW,
                           const float* __restrict__ ipB,
                           const float* __restrict__ opW,
                           const float* __restrict__ opB)
{
    int tid = threadIdx.x;
    float* qvec   = (float*)(g_bytes + B_QVEC);
    float* wscore = (float*)(g_bytes + B_WS);
    float* cscore = (float*)(g_bytes + B_CS);
    float* cpool  = (float*)(g_bytes + B_CP);

    {
        float q = ipB[tid];
        const float* wrow = ipW + (size_t)tid * 128;
        for (int d = 0; d < 128; d++) q += cls[d] * wrow[d];
        qvec[tid] = q;
    }
    __syncthreads();

    const float rs = 0.17677669529663687f;
    for (int idx = tid; idx < 512; idx += 128) {
        int h = idx >> 7, d = idx & 127;
        float s = 0.f;
        for (int e = 0; e < 32; e++)
            s += qvec[h * 32 + e] * ipW[(size_t)(128 + h * 32 + e) * 128 + d];
        wscore[idx] = s * rs;
    }
    if (tid < 4) {
        float s = 0.f;
        for (int e = 0; e < 32; e++)
            s += qvec[tid * 32 + e] * ipB[128 + tid * 32 + e];
        cscore[tid] = s * rs;
    }
    {
        float c = opB[tid];
        const float* orow = opW + (size_t)tid * 128;
        for (int e = 0; e < 128; e++) c += orow[e] * ipB[256 + e];
        cpool[tid] = c;
    }
}

// Mt[d][k] (N-major fp16, 128x512): Mt = (W_v^T W_o^T) transposed
__global__ void prep_M(const float* __restrict__ ipW, const float* __restrict__ opW)
{
    int idx = blockIdx.x * blockDim.x + threadIdx.x;
    if (idx >= 512 * 128) return;
    int d = idx & 127;
    int k = idx >> 7;
    int h = k >> 7;
    int c = k & 127;
    float s = 0.f;
    for (int e = 0; e < 32; e++)
        s += ipW[(size_t)(256 + h * 32 + e) * 128 + c] * opW[(size_t)d * 128 + h * 32 + e];
    ((__half*)(g_bytes + B_MT))[(size_t)d * 512 + k] = __float2half(s);
}

// ---------------------------------------------------------------------------
// weight transpose+convert: W (K x N fp32) -> Wt (N x Kpad fp16), zero-pad k
// ---------------------------------------------------------------------------
__global__ void convT(const float* __restrict__ W, __half* __restrict__ Wt,
                      int K, int N, int Kpad)
{
    __shared__ float tile[32][33];
    int k0 = blockIdx.y * 32, n0 = blockIdx.x * 32;
    int tx = threadIdx.x, ty = threadIdx.y;  // 32 x 8
#pragma unroll
    for (int i = 0; i < 4; i++) {
        int k = k0 + ty + 8 * i, n = n0 + tx;
        tile[ty + 8 * i][tx] = (k < K && n < N) ? W[(size_t)k * N + n] : 0.f;
    }
    __syncthreads();
#pragma unroll
    for (int i = 0; i < 4; i++) {
        int n = n0 + ty + 8 * i, k = k0 + tx;
        if (n < N && k < Kpad)
            Wt[(size_t)n * Kpad + k] = __float2half(tile[tx][ty + 8 * i]);
    }
}

// state -> fp16, padded to 1504 cols (cols >= 1360 zeroed; 1360..1487 later
// overwritten by the pooled GEMM)
__global__ void conv_state(const float* __restrict__ state)
{
    int b = blockIdx.x;
    const float* src = state + (size_t)b * STATE_SZ;
    __half* dst = (__half*)(g_bytes + B_STATEH) + (size_t)b * KPAD0;
    for (int k = threadIdx.x; k < KPAD0; k += 256)
        dst[k] = (k < STATE_SZ) ? __float2half(src[k]) : __float2half(0.f);
}

// ---------------------------------------------------------------------------
// attention kernel: one block per batch item, 128 threads (4 warps)
// ---------------------------------------------------------------------------
__device__ __forceinline__ void slot_info(int s, int& cat, int& off) {
    const int defs[9] = {16, 8, 4, 4, 4, 8, 8, 8, 8};
    int base = 59, acc = 0;
#pragma unroll
    for (int c = 0; c < 9; c++) {
        if (s < acc + defs[c]) { cat = c; off = base + 1 + (s - acc) * 4; return; }
        acc += defs[c];
        base += 1 + defs[c] * 4;
    }
    cat = 8; off = 0;
}

__global__ __launch_bounds__(128)
void attn_k(const float* __restrict__ state,
            const float* __restrict__ embW, const float* __restrict__ embB,
            const float* __restrict__ lng,  const float* __restrict__ lnb,
            const float* __restrict__ cls)
{
    int b = blockIdx.x;
    int tid = threadIdx.x;
    int lane = tid & 31, warp = tid >> 5;

    __shared__ float xs[69][128];
    __shared__ float tokf[68][8];
    __shared__ float sc[4][72];
    __shared__ int s_any;

    const float* st = state + (size_t)b * STATE_SZ;
    float presv = 0.f;
    if (tid < 68) {
        int cat, off;
        slot_info(tid, cat, off);
        float p   = st[1020 + off + 0];
        float dx  = st[1020 + off + 1];
        float dy  = st[1020 + off + 2];
        float di  = st[1020 + off + 3];
        float pp  = st[680 + off + 0];
        float pdx = st[680 + off + 1];
        float pdy = st[680 + off + 2];
        float vv  = (p > 0.5f && pp > 0.5f) ? 1.f : 0.f;
        tokf[tid][0] = dx;
        tokf[tid][1] = dy;
        tokf[tid][2] = di;
        tokf[tid][3] = (dx - pdx) * vv;
        tokf[tid][4] = (dy - pdy) * vv;
        tokf[tid][5] = (float)cat * 0.125f;
        tokf[tid][6] = p;
        presv = p;
    }
    if (tid == 127) s_any = 0;
    __syncthreads();
    if (tid < 68 && presv >= 0.5f) atomicOr(&s_any, 1);
    __syncthreads();
    int all_empty = (s_any == 0);

    const float* wsc = (const float*)(g_bytes + B_WS);
    const float* csc = (const float*)(g_bytes + B_CS);

    for (int j = warp; j < 69; j += 4) {
        float xv[4];
        if (j == 0) {
#pragma unroll
            for (int q = 0; q < 4; q++) xv[q] = cls[lane + 32 * q];
        } else {
            const float* tf = tokf[j - 1];
            float f0 = tf[0], f1 = tf[1], f2 = tf[2], f3 = tf[3], f4 = tf[4], f5 = tf[5], f6 = tf[6];
#pragma unroll
            for (int q = 0; q < 4; q++) {
                int d = lane + 32 * q;
                float e = embB[d];
                e += f0 * embW[0 * 128 + d];
                e += f1 * embW[1 * 128 + d];
                e += f2 * embW[2 * 128 + d];
                e += f3 * embW[3 * 128 + d];
                e += f4 * embW[4 * 128 + d];
                e += f5 * embW[5 * 128 + d];
                e += f6 * embW[6 * 128 + d];
                xv[q] = e;
            }
            float s = xv[0] + xv[1] + xv[2] + xv[3];
            float ss = xv[0]*xv[0] + xv[1]*xv[1] + xv[2]*xv[2] + xv[3]*xv[3];
            s = wsum(s); ss = wsum(ss);
            float mean = s * (1.f / 128.f);
            float var  = ss * (1.f / 128.f) - mean * mean;
            float inv  = rsqrtf(var + 1e-5f);
#pragma unroll
            for (int q = 0; q < 4; q++) {
                int d = lane + 32 * q;
                xv[q] = (xv[q] - mean) * inv * lng[d] + lnb[d];
            }
        }
#pragma unroll
        for (int q = 0; q < 4; q++) xs[j][lane + 32 * q] = xv[q];

        float s0 = 0, s1 = 0, s2 = 0, s3 = 0;
#pragma unroll
        for (int q = 0; q < 4; q++) {
            int d = lane + 32 * q;
            float x = xv[q];
            s0 += x * wsc[d];
            s1 += x * wsc[128 + d];
            s2 += x * wsc[256 + d];
            s3 += x * wsc[384 + d];
        }
        s0 = wsum(s0); s1 = wsum(s1); s2 = wsum(s2); s3 = wsum(s3);
        if (lane == 0) {
            bool masked = (j > 0) && (tokf[j - 1][6] < 0.5f) && !all_empty;
            sc[0][j] = masked ? -1e9f : s0 + csc[0];
            sc[1][j] = masked ? -1e9f : s1 + csc[1];
            sc[2][j] = masked ? -1e9f : s2 + csc[2];
            sc[3][j] = masked ? -1e9f : s3 + csc[3];
        }
    }
    __syncthreads();

    {
        int h = warp;
        float v0 = (lane < 69)      ? sc[h][lane]      : -1e30f;
        float v1 = (lane + 32 < 69) ? sc[h][lane + 32] : -1e30f;
        float v2 = (lane + 64 < 69) ? sc[h][lane + 64] : -1e30f;
        float m = wmax(fmaxf(fmaxf(v0, v1), v2));
        float e0 = (lane < 69)      ? expf(v0 - m) : 0.f;
        float e1 = (lane + 32 < 69) ? expf(v1 - m) : 0.f;
        float e2 = (lane + 64 < 69) ? expf(v2 - m) : 0.f;
        float s = wsum(e0 + e1 + e2);
        float inv = 1.f / s;
        if (lane < 69)      sc[h][lane]      = e0 * inv;
        if (lane + 32 < 69) sc[h][lane + 32] = e1 * inv;
        if (lane + 64 < 69) sc[h][lane + 64] = e2 * inv;
    }
    __syncthreads();

    {
        int d = tid;
        float a0 = 0, a1 = 0, a2 = 0, a3 = 0;
        for (int j = 0; j < 69; j++) {
            float x = xs[j][d];
            a0 += sc[0][j] * x;
            a1 += sc[1][j] * x;
            a2 += sc[2][j] * x;
            a3 += sc[3][j] * x;
        }
        __half* xw = (__half*)(g_bytes + B_XWH) + (size_t)b * 512;
        xw[d]       = __float2half(a0);
        xw[128 + d] = __float2half(a1);
        xw[256 + d] = __float2half(a2);
        xw[384 + d] = __float2half(a3);
    }
}

// ---------------------------------------------------------------------------
// fp16 tensor-core GEMM: C(MxN) = A(MxK) @ Bt^T + bias [+relu]
//   A: M x K fp16 row-major (lda);  Bt: N x K fp16 (N-major, ldb = K)
//   BM=BN=128, BK=32; 256 threads (8 warps, 2x4 of 64x32 warp tiles);
//   3-stage cp.async pipeline; smem row stride 40 halves (conflict-free).
// OUTH: write fp16 C; ACT==1: relu; NGUARD: guard n >= N (B zfill + epilogue)
// ---------------------------------------------------------------------------
constexpr int GSMEM = 3 * 2 * 128 * 40 * 2;  // 61440 bytes

template <bool OUTH, int ACT, bool NGUARD>
__global__ __launch_bounds__(256, 2)
void gemm_f16(int M, int N, int K,
              const __half* __restrict__ A, int lda,
              const __half* __restrict__ Bt,
              const float* __restrict__ bias,
              void* __restrict__ Cv, int ldc)
{
    constexpr int LDS_ = 40;
    extern __shared__ __half sm[];
    __half* Asm = sm;                     // [3][128][40]
    __half* Bsm = sm + 3 * 128 * LDS_;    // [3][128][40]

    int tid = threadIdx.x, lane = tid & 31, warp = tid >> 5;
    int wm = (warp >> 2) * 64, wn = (warp & 3) * 32;
    int bm = blockIdx.y * 128, bn = blockIdx.x * 128;
    int g = lane >> 2, tg = lane & 3;

    float acc[4][4][4];
#pragma unroll
    for (int i = 0; i < 4; i++)
#pragma unroll
        for (int j = 0; j < 4; j++)
#pragma unroll
            for (int c = 0; c < 4; c++) acc[i][j][c] = 0.f;

    auto issue = [&](int t, int s) {
        int k0 = t * 32;
#pragma unroll
        for (int i = 0; i < 2; i++) {
            int c = tid + 256 * i;
            int r = c >> 2, k8 = (c & 3) * 8;
            const __half* src = A + (size_t)(bm + r) * lda + k0 + k8;
            uint32_t dst = (uint32_t)__cvta_generic_to_shared(
                Asm + ((size_t)s * 128 + r) * LDS_ + k8);
            asm volatile("cp.async.cg.shared.global [%0], [%1], 16;\n"
                         :: "r"(dst), "l"(src));
        }
#pragma unroll
        for (int i = 0; i < 2; i++) {
            int c = tid + 256 * i;
            int n = c >> 2, k8 = (c & 3) * 8;
            int gn = bn + n;
            uint32_t dst = (uint32_t)__cvta_generic_to_shared(
                Bsm + ((size_t)s * 128 + n) * LDS_ + k8);
            if (NGUARD) {
                int cn = gn < N ? gn : N - 1;
                const __half* src = Bt + (size_t)cn * K + k0 + k8;
                int sz = gn < N ? 16 : 0;
                asm volatile("cp.async.cg.shared.global [%0], [%1], 16, %2;\n"
                             :: "r"(dst), "l"(src), "r"(sz));
            } else {
                const __half* src = Bt + (size_t)gn * K + k0 + k8;
                asm volatile("cp.async.cg.shared.global [%0], [%1], 16;\n"
                             :: "r"(dst), "l"(src));
            }
        }
        asm volatile("cp.async.commit_group;\n");
    };

    int NT = K / 32;
    issue(0, 0);
    issue(1, 1);

    for (int t = 0; t < NT; t++) {
        int s = t % 3;
        if (t + 1 < NT) asm volatile("cp.async.wait_group 1;\n");
        else            asm volatile("cp.async.wait_group 0;\n");
        __syncthreads();
        if (t + 2 < NT) issue(t + 2, (t + 2) % 3);

        const __half* As = Asm + (size_t)s * 128 * LDS_;
        const __half* Bs = Bsm + (size_t)s * 128 * LDS_;
#pragma unroll
        for (int kk = 0; kk < 2; kk++) {
            int kc = kk * 16;
            uint32_t a[4][4], bf[4][2];
#pragma unroll
            for (int i = 0; i < 4; i++) {
                int r = wm + 16 * i + g;
                a[i][0] = *(const uint32_t*)(As + (size_t)r * LDS_ + kc + 2 * tg);
                a[i][1] = *(const uint32_t*)(As + (size_t)(r + 8) * LDS_ + kc + 2 * tg);
                a[i][2] = *(const uint32_t*)(As + (size_t)r * LDS_ + kc + 8 + 2 * tg);
                a[i][3] = *(const uint32_t*)(As + (size_t)(r + 8) * LDS_ + kc + 8 + 2 * tg);
            }
#pragma unroll
            for (int j = 0; j < 4; j++) {
                int n = wn + 8 * j + g;
                bf[j][0] = *(const uint32_t*)(Bs + (size_t)n * LDS_ + kc + 2 * tg);
                bf[j][1] = *(const uint32_t*)(Bs + (size_t)n * LDS_ + kc + 8 + 2 * tg);
            }
#pragma unroll
            for (int i = 0; i < 4; i++)
#pragma unroll
                for (int j = 0; j < 4; j++) {
                    asm volatile(
                        "mma.sync.aligned.m16n8k16.row.col.f32.f16.f16.f32 "
                        "{%0,%1,%2,%3},{%4,%5,%6,%7},{%8,%9},{%0,%1,%2,%3};"
                        : "+f"(acc[i][j][0]), "+f"(acc[i][j][1]),
                          "+f"(acc[i][j][2]), "+f"(acc[i][j][3])
                        : "r"(a[i][0]), "r"(a[i][1]), "r"(a[i][2]), "r"(a[i][3]),
                          "r"(bf[j][0]), "r"(bf[j][1]));
                }
        }
        __syncthreads();
    }

    // epilogue
    __half* Ch = (__half*)Cv;
    float*  Cf = (float*)Cv;
#pragma unroll
    for (int i = 0; i < 4; i++) {
        int r0 = bm + wm + 16 * i + g;
#pragma unroll
        for (int j = 0; j < 4; j++) {
            int c = bn + wn + 8 * j + 2 * tg;
#pragma unroll
            for (int h = 0; h < 2; h++) {
                int r = r0 + 8 * h;
                float v0 = acc[i][j][2 * h + 0];
                float v1 = acc[i][j][2 * h + 1];
                if (NGUARD) {
                    if (c < N) {
                        float v = v0 + bias[c];
                        if (ACT == 1) v = fmaxf(v, 0.f);
                        if (OUTH) Ch[(size_t)r * ldc + c] = __float2half(v);
                        else      Cf[(size_t)r * ldc + c] = v;
                    }
                    if (c + 1 < N) {
                        float v = v1 + bias[c + 1];
                        if (ACT == 1) v = fmaxf(v, 0.f);
                        if (OUTH) Ch[(size_t)r * ldc + c + 1] = __float2half(v);
                        else      Cf[(size_t)r * ldc + c + 1] = v;
                    }
                } else {
                    float v0b = v0 + bias[c];
                    float v1b = v1 + bias[c + 1];
                    if (ACT == 1) { v0b = fmaxf(v0b, 0.f); v1b = fmaxf(v1b, 0.f); }
                    if (OUTH) {
                        *(__half2*)(Ch + (size_t)r * ldc + c) =
                            __halves2half2(__float2half(v0b), __float2half(v1b));
                    } else {
                        *(float2*)(Cf + (size_t)r * ldc + c) = make_float2(v0b, v1b);
                    }
                }
            }
        }
    }
}

// ---------------------------------------------------------------------------
// rowwise layernorm + relu: fp32 in -> fp16 out, one block per row
// ---------------------------------------------------------------------------
__global__ void ln_relu_k(const float* __restrict__ x, __half* __restrict__ y,
                          const float* __restrict__ g, const float* __restrict__ bta,
                          int L)
{
    size_t row = blockIdx.x;
    const float* p = x + row * (size_t)L;
    __half* q = y + row * (size_t)L;
    int tid = threadIdx.x;
    float s = 0.f, ss = 0.f;
    for (int i = tid; i < L; i += 256) {
        float v = p[i];
        s += v; ss += v * v;
    }
    __shared__ float sh1[8], sh2[8];
    s = wsum(s); ss = wsum(ss);
    int w = tid >> 5, l = tid & 31;
    if (l == 0) { sh1[w] = s; sh2[w] = ss; }
    __syncthreads();
    if (w == 0) {
        float a = (l < 8) ? sh1[l] : 0.f;
        float c = (l < 8) ? sh2[l] : 0.f;
        a = wsum(a); c = wsum(c);
        if (l == 0) { sh1[0] = a; sh2[0] = c; }
    }
    __syncthreads();
    float mean = sh1[0] / (float)L;
    float var  = sh2[0] / (float)L - mean * mean;
    float inv  = rsqrtf(var + 1e-5f);
    for (int i = tid; i < L; i += 256) {
        float v = p[i];
        q[i] = __float2half(fmaxf((v - mean) * inv * g[i] + bta[i], 0.f));
    }
}

// ---------------------------------------------------------------------------
// final dueling head + softmax over atoms; one block per batch item
// ---------------------------------------------------------------------------
__global__ __launch_bounds__(256)
void final_k(const float* __restrict__ valg, const float* __restrict__ advg,
             float* __restrict__ out)
{
    int b = blockIdx.x;
    int tid = threadIdx.x;
    __shared__ float sadv[ADV_N];
    __shared__ float cm[ATOMS];
    __shared__ float sval[ATOMS];
    const float* ap = advg + (size_t)b * ADV_N;
    const float* vp = valg + (size_t)b * ATOMS;
    for (int i = tid; i < ADV_N; i += 256) sadv[i] = ap[i];
    if (tid < ATOMS) sval[tid] = vp[tid];
    __syncthreads();
    if (tid < ATOMS) {
        float s = 0.f;
#pragma unroll
        for (int a = 0; a < ACTIONS; a++) s += sadv[a * ATOMS + tid];
        cm[tid] = s * (1.f / 81.f);
    }
    __syncthreads();
    int w = tid >> 5, l = tid & 31;
    float* op = out + (size_t)b * ADV_N;
    for (int a = w; a < ACTIONS; a += 8) {
        float q0 = (l < ATOMS)      ? sval[l]      + sadv[a * ATOMS + l]      - cm[l]      : -1e30f;
        float q1 = (l + 32 < ATOMS) ? sval[l + 32] + sadv[a * ATOMS + l + 32] - cm[l + 32] : -1e30f;
        float m = wmax(fmaxf(q0, q1));
        float e0 = (l < ATOMS)      ? expf(q0 - m) : 0.f;
        float e1 = (l + 32 < ATOMS) ? expf(q1 - m) : 0.f;
        float sm2 = wsum(e0 + e1);
        float inv = 1.f / sm2;
        if (l < ATOMS)      op[a * ATOMS + l]      = e0 * inv;
        if (l + 32 < ATOMS) op[a * ATOMS + l + 32] = e1 * inv;
    }
}

// ---------------------------------------------------------------------------
extern "C" void kernel_launch(void* const* d_in, const int* in_sizes, int n_in,
                              void* d_out, int out_size)
{
    const float* state     = (const float*)d_in[0];
    const float* embed_W   = (const float*)d_in[1];
    const float* embed_b   = (const float*)d_in[2];
    const float* ln_g      = (const float*)d_in[3];
    const float* ln_b      = (const float*)d_in[4];
    const float* cls_tok   = (const float*)d_in[5];
    const float* in_proj_W = (const float*)d_in[6];
    const float* in_proj_b = (const float*)d_in[7];
    const float* out_proj_W= (const float*)d_in[8];
    const float* out_proj_b= (const float*)d_in[9];
    const float* t0_W      = (const float*)d_in[10];
    const float* t0_b      = (const float*)d_in[11];
    const float* t0_g      = (const float*)d_in[12];
    const float* t0_beta   = (const float*)d_in[13];
    const float* t1_W      = (const float*)d_in[14];
    const float* t1_b      = (const float*)d_in[15];
    const float* t1_g      = (const float*)d_in[16];
    const float* t1_beta   = (const float*)d_in[17];
    const float* val_fc_W  = (const float*)d_in[18];
    const float* val_fc_b  = (const float*)d_in[19];
    const float* val_out_W = (const float*)d_in[20];
    const float* val_out_b = (const float*)d_in[21];
    const float* adv_fc_W  = (const float*)d_in[22];
    const float* adv_fc_b  = (const float*)d_in[23];
    const float* adv_out_W = (const float*)d_in[24];
    const float* adv_out_b = (const float*)d_in[25];
    float* out = (float*)d_out;

    unsigned char* base = nullptr;
    cudaGetSymbolAddress((void**)&base, g_bytes);
    __half* stateH = (__half*)(base + B_STATEH);
    __half* xwH    = (__half*)(base + B_XWH);
    float*  z0     = (float*)(base + B_Z0);
    __half* z0H    = (__half*)(base + B_Z0H);
    float*  h1     = (float*)(base + B_H1);
    __half* h1H    = (__half*)(base + B_H1H);
    __half* valhH  = (__half*)(base + B_VALHH);
    __half* advhH  = (__half*)(base + B_ADVHH);
    float*  val    = (float*)(base + B_VAL);
    float*  adv    = (float*)(base + B_ADV);
    __half* t0Wt   = (__half*)(base + B_T0W);
    __half* t1Wt   = (__half*)(base + B_T1W);
    __half* vfcWt  = (__half*)(base + B_VFCW);
    __half* afcWt  = (__half*)(base + B_AFCW);
    __half* voWt   = (__half*)(base + B_VOW);
    __half* aoWt   = (__half*)(base + B_AOW);
    __half* Mt     = (__half*)(base + B_MT);
    float*  cpool  = (float*)(base + B_CP);

    cudaFuncSetAttribute(gemm_f16<true, 0, false>,
                         cudaFuncAttributeMaxDynamicSharedMemorySize, GSMEM);
    cudaFuncSetAttribute(gemm_f16<false, 0, false>,
                         cudaFuncAttributeMaxDynamicSharedMemorySize, GSMEM);
    cudaFuncSetAttribute(gemm_f16<true, 1, false>,
                         cudaFuncAttributeMaxDynamicSharedMemorySize, GSMEM);
    cudaFuncSetAttribute(gemm_f16<false, 0, true>,
                         cudaFuncAttributeMaxDynamicSharedMemorySize, GSMEM);

    dim3 t32x8(32, 8);
    conv_state<<<BQ, 256>>>(state);
    convT<<<dim3(32, 47), t32x8>>>(t0_W, t0Wt, 1488, 1024, KPAD0);
    convT<<<dim3(32, 32), t32x8>>>(t1_W, t1Wt, 1024, 1024, 1024);
    convT<<<dim3(16, 32), t32x8>>>(val_fc_W, vfcWt, 1024, 512, 1024);
    convT<<<dim3(16, 32), t32x8>>>(adv_fc_W, afcWt, 1024, 512, 1024);
    convT<<<dim3(2, 16),  t32x8>>>(val_out_W, voWt, 512, ATOMS, 512);
    convT<<<dim3(130, 16), t32x8>>>(adv_out_W, aoWt, 512, ADV_N, 512);

    prep_small<<<1, 128>>>(cls_tok, in_proj_W, in_proj_b, out_proj_W, out_proj_b);
    prep_M<<<256, 256>>>(in_proj_W, out_proj_W);

    attn_k<<<BQ, 128>>>(state, embed_W, embed_b, ln_g, ln_b, cls_tok);

    // pooled (fp16) -> stateH cols 1360..1487
    gemm_f16<true, 0, false><<<dim3(1, 64), 256, GSMEM>>>(
        BQ, 128, 512, xwH, 512, Mt, cpool, stateH + 1360, KPAD0);

    // trunk 0
    gemm_f16<false, 0, false><<<dim3(8, 64), 256, GSMEM>>>(
        BQ, TRUNK_H, KPAD0, stateH, KPAD0, t0Wt, t0_b, z0, TRUNK_H);
    ln_relu_k<<<BQ, 256>>>(z0, z0H, t0_g, t0_beta, TRUNK_H);

    // trunk 1
    gemm_f16<false, 0, false><<<dim3(8, 64), 256, GSMEM>>>(
        BQ, TRUNK_H, TRUNK_H, z0H, TRUNK_H, t1Wt, t1_b, h1, TRUNK_H);
    ln_relu_k<<<BQ, 256>>>(h1, h1H, t1_g, t1_beta, TRUNK_H);

    // heads (relu fused, fp16 out)
    gemm_f16<true, 1, false><<<dim3(4, 64), 256, GSMEM>>>(
        BQ, HALF_H, TRUNK_H, h1H, TRUNK_H, vfcWt, val_fc_b, valhH, HALF_H);
    gemm_f16<true, 1, false><<<dim3(4, 64), 256, GSMEM>>>(
        BQ, HALF_H, TRUNK_H, h1H, TRUNK_H, afcWt, adv_fc_b, advhH, HALF_H);

    gemm_f16<false, 0, true><<<dim3(1, 64), 256, GSMEM>>>(
        BQ, ATOMS, HALF_H, valhH, HALF_H, voWt, val_out_b, val, ATOMS);
    gemm_f16<false, 0, true><<<dim3(33, 64), 256, GSMEM>>>(
        BQ, ADV_N, HALF_H, advhH, HALF_H, aoWt, adv_out_b, adv, ADV_N);

    final_k<<<BQ, 256>>>(val, adv, out);
    (void)in_sizes; (void)n_in; (void)out_size;
}

// round 7
// speedup vs baseline: 1.6022x; 1.6022x over previous
#include <cuda_runtime.h>
#include <cuda_fp16.h>
#include <math.h>
#include <stdint.h>

// ---------------------------------------------------------------------------
// RainbowNet fused inference — fp16 warp-MMA + ldmatrix edition.
// Attention folded (cls query is batch-independent):
//   scores[h,j] = x_j . wscore_h + c_h ;  pooled = XW @ Mflat + c_pool
// GEMMs: mma.sync.m16n8k16 f16 (fp32 accum), 3-stage cp.async pipeline,
// ldmatrix.x4 fragment loads (R6 delta vs R3's scalar LDS loads).
// ---------------------------------------------------------------------------

constexpr int BQ       = 8192;
constexpr int STATE_SZ = 1360;
constexpr int KPAD0    = 1504;   // 1488 padded to multiple of 32
constexpr int TRUNK_H  = 1024;
constexpr int HALF_H   = 512;
constexpr int ATOMS    = 51;
constexpr int ACTIONS  = 81;
constexpr int ADV_N    = ACTIONS * ATOMS;  // 4131

// byte offsets into g_bytes
constexpr size_t B_STATEH = 0;                       // 8192*1504 h
constexpr size_t B_XWH    = 24641536;                // 8192*512 h
constexpr size_t B_Z0     = 33030144;                // 8192*1024 f
constexpr size_t B_Z0H    = 66584576;                // 8192*1024 h
constexpr size_t B_H1     = 83361792;                // 8192*1024 f
constexpr size_t B_H1H    = 116916224;               // 8192*1024 h
constexpr size_t B_VALHH  = 133693440;               // 8192*512 h
constexpr size_t B_ADVHH  = 142082048;               // 8192*512 h
constexpr size_t B_VAL    = 150470656;               // 8192*51 f
constexpr size_t B_ADV    = 152141824;               // 8192*4131 f
constexpr size_t B_T0W    = 287506432;               // 1024*1504 h
constexpr size_t B_T1W    = 290586624;               // 1024*1024 h
constexpr size_t B_VFCW   = 292683776;               // 512*1024 h
constexpr size_t B_AFCW   = 293732352;               // 512*1024 h
constexpr size_t B_VOW    = 294780928;               // 51*512 h
constexpr size_t B_AOW    = 294833152;               // 4131*512 h
constexpr size_t B_MT     = 299063296;               // 128*512 h
constexpr size_t B_QVEC   = 299194368;               // 128 f
constexpr size_t B_WS     = 299194880;               // 512 f
constexpr size_t B_CS     = 299196928;               // 4 f (pad 64)
constexpr size_t B_CP     = 299196992;               // 128 f
constexpr size_t B_TOTAL  = 299197504;

__device__ __align__(256) unsigned char g_bytes[B_TOTAL];

__device__ __forceinline__ float wsum(float v) {
#pragma unroll
    for (int o = 16; o > 0; o >>= 1) v += __shfl_xor_sync(0xffffffffu, v, o);
    return v;
}
__device__ __forceinline__ float wmax(float v) {
#pragma unroll
    for (int o = 16; o > 0; o >>= 1) v = fmaxf(v, __shfl_xor_sync(0xffffffffu, v, o));
    return v;
}

// ---------------------------------------------------------------------------
// prep_small: qvec, wscore, cscore, cpool   (1 block, 128 threads)
// ---------------------------------------------------------------------------
__global__ void prep_small(const float* __restrict__ cls,
                           const float* __restrict__ ipW,
                           const float* __restrict__ ipB,
                           const float* __restrict__ opW,
                           const float* __restrict__ opB)
{
    int tid = threadIdx.x;
    float* qvec   = (float*)(g_bytes + B_QVEC);
    float* wscore = (float*)(g_bytes + B_WS);
    float* cscore = (float*)(g_bytes + B_CS);
    float* cpool  = (float*)(g_bytes + B_CP);

    {
        float q = ipB[tid];
        const float* wrow = ipW + (size_t)tid * 128;
        for (int d = 0; d < 128; d++) q += cls[d] * wrow[d];
        qvec[tid] = q;
    }
    __syncthreads();

    const float rs = 0.17677669529663687f;
    for (int idx = tid; idx < 512; idx += 128) {
        int h = idx >> 7, d = idx & 127;
        float s = 0.f;
        for (int e = 0; e < 32; e++)
            s += qvec[h * 32 + e] * ipW[(size_t)(128 + h * 32 + e) * 128 + d];
        wscore[idx] = s * rs;
    }
    if (tid < 4) {
        float s = 0.f;
        for (int e = 0; e < 32; e++)
            s += qvec[tid * 32 + e] * ipB[128 + tid * 32 + e];
        cscore[tid] = s * rs;
    }
    {
        float c = opB[tid];
        const float* orow = opW + (size_t)tid * 128;
        for (int e = 0; e < 128; e++) c += orow[e] * ipB[256 + e];
        cpool[tid] = c;
    }
}

// Mt[d][k] (N-major fp16, 128x512)
__global__ void prep_M(const float* __restrict__ ipW, const float* __restrict__ opW)
{
    int idx = blockIdx.x * blockDim.x + threadIdx.x;
    if (idx >= 512 * 128) return;
    int d = idx & 127;
    int k = idx >> 7;
    int h = k >> 7;
    int c = k & 127;
    float s = 0.f;
    for (int e = 0; e < 32; e++)
        s += ipW[(size_t)(256 + h * 32 + e) * 128 + c] * opW[(size_t)d * 128 + h * 32 + e];
    ((__half*)(g_bytes + B_MT))[(size_t)d * 512 + k] = __float2half(s);
}

// ---------------------------------------------------------------------------
// weight transpose+convert: W (K x N fp32) -> Wt (N x Kpad fp16), zero-pad k
// ---------------------------------------------------------------------------
__global__ void convT(const float* __restrict__ W, __half* __restrict__ Wt,
                      int K, int N, int Kpad)
{
    __shared__ float tile[32][33];
    int k0 = blockIdx.y * 32, n0 = blockIdx.x * 32;
    int tx = threadIdx.x, ty = threadIdx.y;  // 32 x 8
#pragma unroll
    for (int i = 0; i < 4; i++) {
        int k = k0 + ty + 8 * i, n = n0 + tx;
        tile[ty + 8 * i][tx] = (k < K && n < N) ? W[(size_t)k * N + n] : 0.f;
    }
    __syncthreads();
#pragma unroll
    for (int i = 0; i < 4; i++) {
        int n = n0 + ty + 8 * i, k = k0 + tx;
        if (n < N && k < Kpad)
            Wt[(size_t)n * Kpad + k] = __float2half(tile[tx][ty + 8 * i]);
    }
}

__global__ void conv_state(const float* __restrict__ state)
{
    int b = blockIdx.x;
    const float* src = state + (size_t)b * STATE_SZ;
    __half* dst = (__half*)(g_bytes + B_STATEH) + (size_t)b * KPAD0;
    for (int k = threadIdx.x; k < KPAD0; k += 256)
        dst[k] = (k < STATE_SZ) ? __float2half(src[k]) : __float2half(0.f);
}

// ---------------------------------------------------------------------------
// attention kernel: one block per batch item, 128 threads (4 warps)
// ---------------------------------------------------------------------------
__device__ __forceinline__ void slot_info(int s, int& cat, int& off) {
    const int defs[9] = {16, 8, 4, 4, 4, 8, 8, 8, 8};
    int base = 59, acc = 0;
#pragma unroll
    for (int c = 0; c < 9; c++) {
        if (s < acc + defs[c]) { cat = c; off = base + 1 + (s - acc) * 4; return; }
        acc += defs[c];
        base += 1 + defs[c] * 4;
    }
    cat = 8; off = 0;
}

__global__ __launch_bounds__(128)
void attn_k(const float* __restrict__ state,
            const float* __restrict__ embW, const float* __restrict__ embB,
            const float* __restrict__ lng,  const float* __restrict__ lnb,
            const float* __restrict__ cls)
{
    int b = blockIdx.x;
    int tid = threadIdx.x;
    int lane = tid & 31, warp = tid >> 5;

    __shared__ float xs[69][128];
    __shared__ float tokf[68][8];
    __shared__ float sc[4][72];
    __shared__ int s_any;

    const float* st = state + (size_t)b * STATE_SZ;
    float presv = 0.f;
    if (tid < 68) {
        int cat, off;
        slot_info(tid, cat, off);
        float p   = st[1020 + off + 0];
        float dx  = st[1020 + off + 1];
        float dy  = st[1020 + off + 2];
        float di  = st[1020 + off + 3];
        float pp  = st[680 + off + 0];
        float pdx = st[680 + off + 1];
        float pdy = st[680 + off + 2];
        float vv  = (p > 0.5f && pp > 0.5f) ? 1.f : 0.f;
        tokf[tid][0] = dx;
        tokf[tid][1] = dy;
        tokf[tid][2] = di;
        tokf[tid][3] = (dx - pdx) * vv;
        tokf[tid][4] = (dy - pdy) * vv;
        tokf[tid][5] = (float)cat * 0.125f;
        tokf[tid][6] = p;
        presv = p;
    }
    if (tid == 127) s_any = 0;
    __syncthreads();
    if (tid < 68 && presv >= 0.5f) atomicOr(&s_any, 1);
    __syncthreads();
    int all_empty = (s_any == 0);

    const float* wsc = (const float*)(g_bytes + B_WS);
    const float* csc = (const float*)(g_bytes + B_CS);

    for (int j = warp; j < 69; j += 4) {
        float xv[4];
        if (j == 0) {
#pragma unroll
            for (int q = 0; q < 4; q++) xv[q] = cls[lane + 32 * q];
        } else {
            const float* tf = tokf[j - 1];
            float f0 = tf[0], f1 = tf[1], f2 = tf[2], f3 = tf[3], f4 = tf[4], f5 = tf[5], f6 = tf[6];
#pragma unroll
            for (int q = 0; q < 4; q++) {
                int d = lane + 32 * q;
                float e = embB[d];
                e += f0 * embW[0 * 128 + d];
                e += f1 * embW[1 * 128 + d];
                e += f2 * embW[2 * 128 + d];
                e += f3 * embW[3 * 128 + d];
                e += f4 * embW[4 * 128 + d];
                e += f5 * embW[5 * 128 + d];
                e += f6 * embW[6 * 128 + d];
                xv[q] = e;
            }
            float s = xv[0] + xv[1] + xv[2] + xv[3];
            float ss = xv[0]*xv[0] + xv[1]*xv[1] + xv[2]*xv[2] + xv[3]*xv[3];
            s = wsum(s); ss = wsum(ss);
            float mean = s * (1.f / 128.f);
            float var  = ss * (1.f / 128.f) - mean * mean;
            float inv  = rsqrtf(var + 1e-5f);
#pragma unroll
            for (int q = 0; q < 4; q++) {
                int d = lane + 32 * q;
                xv[q] = (xv[q] - mean) * inv * lng[d] + lnb[d];
            }
        }
#pragma unroll
        for (int q = 0; q < 4; q++) xs[j][lane + 32 * q] = xv[q];

        float s0 = 0, s1 = 0, s2 = 0, s3 = 0;
#pragma unroll
        for (int q = 0; q < 4; q++) {
            int d = lane + 32 * q;
            float x = xv[q];
            s0 += x * wsc[d];
            s1 += x * wsc[128 + d];
            s2 += x * wsc[256 + d];
            s3 += x * wsc[384 + d];
        }
        s0 = wsum(s0); s1 = wsum(s1); s2 = wsum(s2); s3 = wsum(s3);
        if (lane == 0) {
            bool masked = (j > 0) && (tokf[j - 1][6] < 0.5f) && !all_empty;
            sc[0][j] = masked ? -1e9f : s0 + csc[0];
            sc[1][j] = masked ? -1e9f : s1 + csc[1];
            sc[2][j] = masked ? -1e9f : s2 + csc[2];
            sc[3][j] = masked ? -1e9f : s3 + csc[3];
        }
    }
    __syncthreads();

    {
        int h = warp;
        float v0 = (lane < 69)      ? sc[h][lane]      : -1e30f;
        float v1 = (lane + 32 < 69) ? sc[h][lane + 32] : -1e30f;
        float v2 = (lane + 64 < 69) ? sc[h][lane + 64] : -1e30f;
        float m = wmax(fmaxf(fmaxf(v0, v1), v2));
        float e0 = (lane < 69)      ? expf(v0 - m) : 0.f;
        float e1 = (lane + 32 < 69) ? expf(v1 - m) : 0.f;
        float e2 = (lane + 64 < 69) ? expf(v2 - m) : 0.f;
        float s = wsum(e0 + e1 + e2);
        float inv = 1.f / s;
        if (lane < 69)      sc[h][lane]      = e0 * inv;
        if (lane + 32 < 69) sc[h][lane + 32] = e1 * inv;
        if (lane + 64 < 69) sc[h][lane + 64] = e2 * inv;
    }
    __syncthreads();

    {
        int d = tid;
        float a0 = 0, a1 = 0, a2 = 0, a3 = 0;
        for (int j = 0; j < 69; j++) {
            float x = xs[j][d];
            a0 += sc[0][j] * x;
            a1 += sc[1][j] * x;
            a2 += sc[2][j] * x;
            a3 += sc[3][j] * x;
        }
        __half* xw = (__half*)(g_bytes + B_XWH) + (size_t)b * 512;
        xw[d]       = __float2half(a0);
        xw[128 + d] = __float2half(a1);
        xw[256 + d] = __float2half(a2);
        xw[384 + d] = __float2half(a3);
    }
}

// ---------------------------------------------------------------------------
// fp16 tensor-core GEMM with ldmatrix fragment loads.
//   C(MxN) = A(MxK fp16 rowmaj, lda) @ Bt(N x K fp16 N-major)^T + bias [+relu]
//   BM=BN=128, BK=32; 256 threads (8 warps, 2x4 of 64x32 warp tiles);
//   3-stage cp.async pipeline; smem row stride 40 halves (LDSM conflict-free).
// ---------------------------------------------------------------------------
constexpr int GSMEM = 3 * 2 * 128 * 40 * 2;  // 61440 bytes

template <bool OUTH, int ACT, bool NGUARD>
__global__ __launch_bounds__(256, 2)
void gemm_f16(int M, int N, int K,
              const __half* __restrict__ A, int lda,
              const __half* __restrict__ Bt,
              const float* __restrict__ bias,
              void* __restrict__ Cv, int ldc)
{
    constexpr int LDS_ = 40;                 // halves per smem row
    constexpr int ROWB = LDS_ * 2;           // 80 bytes per row
    extern __shared__ __half sm[];
    __half* Asm = sm;                     // [3][128][40]
    __half* Bsm = sm + 3 * 128 * LDS_;    // [3][128][40]

    int tid = threadIdx.x, lane = tid & 31, warp = tid >> 5;
    int wm = (warp >> 2) * 64, wn = (warp & 3) * 32;
    int bm = blockIdx.y * 128, bn = blockIdx.x * 128;
    int g = lane >> 2, tg = lane & 3;        // epilogue mapping
    int lg = lane >> 3, lr = lane & 7;       // ldmatrix lane groups

    // ldmatrix per-lane byte offsets (within one stage)
    uint32_t aBase, bBase;
    {
        uint64_t t = (uint64_t)__cvta_generic_to_shared(Asm);
        aBase = (uint32_t)t;
        t = (uint64_t)__cvta_generic_to_shared(Bsm);
        bBase = (uint32_t)t;
    }
    // A x4 tiles: (m0-7,k0),(m8-15,k0),(m0-7,k8),(m8-15,k8)
    uint32_t aOffL = (uint32_t)((wm + (lg & 1) * 8 + lr) * ROWB + (lg >> 1) * 16);
    // B x4 tiles: (n0-7,k0),(n0-7,k8),(n8-15,k0),(n8-15,k8)
    uint32_t bOffL = (uint32_t)((wn + (lg >> 1) * 8 + lr) * ROWB + (lg & 1) * 16);

    float acc[4][4][4];
#pragma unroll
    for (int i = 0; i < 4; i++)
#pragma unroll
        for (int j = 0; j < 4; j++)
#pragma unroll
            for (int c = 0; c < 4; c++) acc[i][j][c] = 0.f;

    auto issue = [&](int t, int s) {
        int k0 = t * 32;
#pragma unroll
        for (int i = 0; i < 2; i++) {
            int c = tid + 256 * i;
            int r = c >> 2, k8 = (c & 3) * 8;
            const __half* src = A + (size_t)(bm + r) * lda + k0 + k8;
            uint32_t dst = (uint32_t)__cvta_generic_to_shared(
                Asm + ((size_t)s * 128 + r) * LDS_ + k8);
            asm volatile("cp.async.cg.shared.global [%0], [%1], 16;\n"
                         :: "r"(dst), "l"(src));
        }
#pragma unroll
        for (int i = 0; i < 2; i++) {
            int c = tid + 256 * i;
            int n = c >> 2, k8 = (c & 3) * 8;
            int gn = bn + n;
            uint32_t dst = (uint32_t)__cvta_generic_to_shared(
                Bsm + ((size_t)s * 128 + n) * LDS_ + k8);
            if (NGUARD) {
                int cn = gn < N ? gn : N - 1;
                const __half* src = Bt + (size_t)cn * K + k0 + k8;
                int sz = gn < N ? 16 : 0;
                asm volatile("cp.async.cg.shared.global [%0], [%1], 16, %2;\n"
                             :: "r"(dst), "l"(src), "r"(sz));
            } else {
                const __half* src = Bt + (size_t)gn * K + k0 + k8;
                asm volatile("cp.async.cg.shared.global [%0], [%1], 16;\n"
                             :: "r"(dst), "l"(src));
            }
        }
        asm volatile("cp.async.commit_group;\n");
    };

    int NT = K / 32;
    issue(0, 0);
    issue(1, 1);

    for (int t = 0; t < NT; t++) {
        int s = t % 3;
        if (t + 1 < NT) asm volatile("cp.async.wait_group 1;\n");
        else            asm volatile("cp.async.wait_group 0;\n");
        __syncthreads();
        if (t + 2 < NT) issue(t + 2, (t + 2) % 3);

        uint32_t aS = aBase + (uint32_t)(s * 128 * ROWB);
        uint32_t bS = bBase + (uint32_t)(s * 128 * ROWB);
#pragma unroll
        for (int kk = 0; kk < 2; kk++) {
            uint32_t kby = (uint32_t)(kk * 32);  // 16 halves
            uint32_t a[4][4];
#pragma unroll
            for (int i = 0; i < 4; i++) {
                uint32_t addr = aS + aOffL + (uint32_t)(i * 16 * ROWB) + kby;
                asm volatile(
                    "ldmatrix.sync.aligned.m8n8.x4.shared.b16 {%0,%1,%2,%3}, [%4];"
                    : "=r"(a[i][0]), "=r"(a[i][1]), "=r"(a[i][2]), "=r"(a[i][3])
                    : "r"(addr));
            }
            uint32_t bf[4][2];
#pragma unroll
            for (int j2 = 0; j2 < 2; j2++) {
                uint32_t addr = bS + bOffL + (uint32_t)(j2 * 16 * ROWB) + kby;
                asm volatile(
                    "ldmatrix.sync.aligned.m8n8.x4.shared.b16 {%0,%1,%2,%3}, [%4];"
                    : "=r"(bf[2 * j2][0]), "=r"(bf[2 * j2][1]),
                      "=r"(bf[2 * j2 + 1][0]), "=r"(bf[2 * j2 + 1][1])
                    : "r"(addr));
            }
#pragma unroll
            for (int i = 0; i < 4; i++)
#pragma unroll
                for (int j = 0; j < 4; j++) {
                    asm volatile(
                        "mma.sync.aligned.m16n8k16.row.col.f32.f16.f16.f32 "
                        "{%0,%1,%2,%3},{%4,%5,%6,%7},{%8,%9},{%0,%1,%2,%3};"
                        : "+f"(acc[i][j][0]), "+f"(acc[i][j][1]),
                          "+f"(acc[i][j][2]), "+f"(acc[i][j][3])
                        : "r"(a[i][0]), "r"(a[i][1]), "r"(a[i][2]), "r"(a[i][3]),
                          "r"(bf[j][0]), "r"(bf[j][1]));
                }
        }
        __syncthreads();
    }

    // epilogue
    __half* Ch = (__half*)Cv;
    float*  Cf = (float*)Cv;
#pragma unroll
    for (int i = 0; i < 4; i++) {
        int r0 = bm + wm + 16 * i + g;
#pragma unroll
        for (int j = 0; j < 4; j++) {
            int c = bn + wn + 8 * j + 2 * tg;
#pragma unroll
            for (int h = 0; h < 2; h++) {
                int r = r0 + 8 * h;
                float v0 = acc[i][j][2 * h + 0];
                float v1 = acc[i][j][2 * h + 1];
                if (NGUARD) {
                    if (c < N) {
                        float v = v0 + bias[c];
                        if (ACT == 1) v = fmaxf(v, 0.f);
                        if (OUTH) Ch[(size_t)r * ldc + c] = __float2half(v);
                        else      Cf[(size_t)r * ldc + c] = v;
                    }
                    if (c + 1 < N) {
                        float v = v1 + bias[c + 1];
                        if (ACT == 1) v = fmaxf(v, 0.f);
                        if (OUTH) Ch[(size_t)r * ldc + c + 1] = __float2half(v);
                        else      Cf[(size_t)r * ldc + c + 1] = v;
                    }
                } else {
                    float v0b = v0 + bias[c];
                    float v1b = v1 + bias[c + 1];
                    if (ACT == 1) { v0b = fmaxf(v0b, 0.f); v1b = fmaxf(v1b, 0.f); }
                    if (OUTH) {
                        *(__half2*)(Ch + (size_t)r * ldc + c) =
                            __halves2half2(__float2half(v0b), __float2half(v1b));
                    } else {
                        *(float2*)(Cf + (size_t)r * ldc + c) = make_float2(v0b, v1b);
                    }
                }
            }
        }
    }
}

// ---------------------------------------------------------------------------
// rowwise layernorm + relu: fp32 in -> fp16 out, one block per row
// ---------------------------------------------------------------------------
__global__ void ln_relu_k(const float* __restrict__ x, __half* __restrict__ y,
                          const float* __restrict__ g, const float* __restrict__ bta,
                          int L)
{
    size_t row = blockIdx.x;
    const float* p = x + row * (size_t)L;
    __half* q = y + row * (size_t)L;
    int tid = threadIdx.x;
    float s = 0.f, ss = 0.f;
    for (int i = tid; i < L; i += 256) {
        float v = p[i];
        s += v; ss += v * v;
    }
    __shared__ float sh1[8], sh2[8];
    s = wsum(s); ss = wsum(ss);
    int w = tid >> 5, l = tid & 31;
    if (l == 0) { sh1[w] = s; sh2[w] = ss; }
    __syncthreads();
    if (w == 0) {
        float a = (l < 8) ? sh1[l] : 0.f;
        float c = (l < 8) ? sh2[l] : 0.f;
        a = wsum(a); c = wsum(c);
        if (l == 0) { sh1[0] = a; sh2[0] = c; }
    }
    __syncthreads();
    float mean = sh1[0] / (float)L;
    float var  = sh2[0] / (float)L - mean * mean;
    float inv  = rsqrtf(var + 1e-5f);
    for (int i = tid; i < L; i += 256) {
        float v = p[i];
        q[i] = __float2half(fmaxf((v - mean) * inv * g[i] + bta[i], 0.f));
    }
}

// ---------------------------------------------------------------------------
// final dueling head + softmax over atoms; one block per batch item
// ---------------------------------------------------------------------------
__global__ __launch_bounds__(256)
void final_k(const float* __restrict__ valg, const float* __restrict__ advg,
             float* __restrict__ out)
{
    int b = blockIdx.x;
    int tid = threadIdx.x;
    __shared__ float sadv[ADV_N];
    __shared__ float cm[ATOMS];
    __shared__ float sval[ATOMS];
    const float* ap = advg + (size_t)b * ADV_N;
    const float* vp = valg + (size_t)b * ATOMS;
    for (int i = tid; i < ADV_N; i += 256) sadv[i] = ap[i];
    if (tid < ATOMS) sval[tid] = vp[tid];
    __syncthreads();
    if (tid < ATOMS) {
        float s = 0.f;
#pragma unroll
        for (int a = 0; a < ACTIONS; a++) s += sadv[a * ATOMS + tid];
        cm[tid] = s * (1.f / 81.f);
    }
    __syncthreads();
    int w = tid >> 5, l = tid & 31;
    float* op = out + (size_t)b * ADV_N;
    for (int a = w; a < ACTIONS; a += 8) {
        float q0 = (l < ATOMS)      ? sval[l]      + sadv[a * ATOMS + l]      - cm[l]      : -1e30f;
        float q1 = (l + 32 < ATOMS) ? sval[l + 32] + sadv[a * ATOMS + l + 32] - cm[l + 32] : -1e30f;
        float m = wmax(fmaxf(q0, q1));
        float e0 = (l < ATOMS)      ? expf(q0 - m) : 0.f;
        float e1 = (l + 32 < ATOMS) ? expf(q1 - m) : 0.f;
        float sm2 = wsum(e0 + e1);
        float inv = 1.f / sm2;
        if (l < ATOMS)      op[a * ATOMS + l]      = e0 * inv;
        if (l + 32 < ATOMS) op[a * ATOMS + l + 32] = e1 * inv;
    }
}

// ---------------------------------------------------------------------------
extern "C" void kernel_launch(void* const* d_in, const int* in_sizes, int n_in,
                              void* d_out, int out_size)
{
    const float* state     = (const float*)d_in[0];
    const float* embed_W   = (const float*)d_in[1];
    const float* embed_b   = (const float*)d_in[2];
    const float* ln_g      = (const float*)d_in[3];
    const float* ln_b      = (const float*)d_in[4];
    const float* cls_tok   = (const float*)d_in[5];
    const float* in_proj_W = (const float*)d_in[6];
    const float* in_proj_b = (const float*)d_in[7];
    const float* out_proj_W= (const float*)d_in[8];
    const float* out_proj_b= (const float*)d_in[9];
    const float* t0_W      = (const float*)d_in[10];
    const float* t0_b      = (const float*)d_in[11];
    const float* t0_g      = (const float*)d_in[12];
    const float* t0_beta   = (const float*)d_in[13];
    const float* t1_W      = (const float*)d_in[14];
    const float* t1_b      = (const float*)d_in[15];
    const float* t1_g      = (const float*)d_in[16];
    const float* t1_beta   = (const float*)d_in[17];
    const float* val_fc_W  = (const float*)d_in[18];
    const float* val_fc_b  = (const float*)d_in[19];
    const float* val_out_W = (const float*)d_in[20];
    const float* val_out_b = (const float*)d_in[21];
    const float* adv_fc_W  = (const float*)d_in[22];
    const float* adv_fc_b  = (const float*)d_in[23];
    const float* adv_out_W = (const float*)d_in[24];
    const float* adv_out_b = (const float*)d_in[25];
    float* out = (float*)d_out;

    unsigned char* base = nullptr;
    cudaGetSymbolAddress((void**)&base, g_bytes);
    __half* stateH = (__half*)(base + B_STATEH);
    __half* xwH    = (__half*)(base + B_XWH);
    float*  z0     = (float*)(base + B_Z0);
    __half* z0H    = (__half*)(base + B_Z0H);
    float*  h1     = (float*)(base + B_H1);
    __half* h1H    = (__half*)(base + B_H1H);
    __half* valhH  = (__half*)(base + B_VALHH);
    __half* advhH  = (__half*)(base + B_ADVHH);
    float*  val    = (float*)(base + B_VAL);
    float*  adv    = (float*)(base + B_ADV);
    __half* t0Wt   = (__half*)(base + B_T0W);
    __half* t1Wt   = (__half*)(base + B_T1W);
    __half* vfcWt  = (__half*)(base + B_VFCW);
    __half* afcWt  = (__half*)(base + B_AFCW);
    __half* voWt   = (__half*)(base + B_VOW);
    __half* aoWt   = (__half*)(base + B_AOW);
    __half* Mt     = (__half*)(base + B_MT);
    float*  cpool  = (float*)(base + B_CP);

    cudaFuncSetAttribute(gemm_f16<true, 0, false>,
                         cudaFuncAttributeMaxDynamicSharedMemorySize, GSMEM);
    cudaFuncSetAttribute(gemm_f16<false, 0, false>,
                         cudaFuncAttributeMaxDynamicSharedMemorySize, GSMEM);
    cudaFuncSetAttribute(gemm_f16<true, 1, false>,
                         cudaFuncAttributeMaxDynamicSharedMemorySize, GSMEM);
    cudaFuncSetAttribute(gemm_f16<false, 0, true>,
                         cudaFuncAttributeMaxDynamicSharedMemorySize, GSMEM);

    dim3 t32x8(32, 8);
    conv_state<<<BQ, 256>>>(state);
    convT<<<dim3(32, 47), t32x8>>>(t0_W, t0Wt, 1488, 1024, KPAD0);
    convT<<<dim3(32, 32), t32x8>>>(t1_W, t1Wt, 1024, 1024, 1024);
    convT<<<dim3(16, 32), t32x8>>>(val_fc_W, vfcWt, 1024, 512, 1024);
    convT<<<dim3(16, 32), t32x8>>>(adv_fc_W, afcWt, 1024, 512, 1024);
    convT<<<dim3(2, 16),  t32x8>>>(val_out_W, voWt, 512, ATOMS, 512);
    convT<<<dim3(130, 16), t32x8>>>(adv_out_W, aoWt, 512, ADV_N, 512);

    prep_small<<<1, 128>>>(cls_tok, in_proj_W, in_proj_b, out_proj_W, out_proj_b);
    prep_M<<<256, 256>>>(in_proj_W, out_proj_W);

    attn_k<<<BQ, 128>>>(state, embed_W, embed_b, ln_g, ln_b, cls_tok);

    // pooled (fp16) -> stateH cols 1360..1487
    gemm_f16<true, 0, false><<<dim3(1, 64), 256, GSMEM>>>(
        BQ, 128, 512, xwH, 512, Mt, cpool, stateH + 1360, KPAD0);

    // trunk 0
    gemm_f16<false, 0, false><<<dim3(8, 64), 256, GSMEM>>>(
        BQ, TRUNK_H, KPAD0, stateH, KPAD0, t0Wt, t0_b, z0, TRUNK_H);
    ln_relu_k<<<BQ, 256>>>(z0, z0H, t0_g, t0_beta, TRUNK_H);

    // trunk 1
    gemm_f16<false, 0, false><<<dim3(8, 64), 256, GSMEM>>>(
        BQ, TRUNK_H, TRUNK_H, z0H, TRUNK_H, t1Wt, t1_b, h1, TRUNK_H);
    ln_relu_k<<<BQ, 256>>>(h1, h1H, t1_g, t1_beta, TRUNK_H);

    // heads (relu fused, fp16 out)
    gemm_f16<true, 1, false><<<dim3(4, 64), 256, GSMEM>>>(
        BQ, HALF_H, TRUNK_H, h1H, TRUNK_H, vfcWt, val_fc_b, valhH, HALF_H);
    gemm_f16<true, 1, false><<<dim3(4, 64), 256, GSMEM>>>(
        BQ, HALF_H, TRUNK_H, h1H, TRUNK_H, afcWt, adv_fc_b, advhH, HALF_H);

    gemm_f16<false, 0, true><<<dim3(1, 64), 256, GSMEM>>>(
        BQ, ATOMS, HALF_H, valhH, HALF_H, voWt, val_out_b, val, ATOMS);
    gemm_f16<false, 0, true><<<dim3(33, 64), 256, GSMEM>>>(
        BQ, ADV_N, HALF_H, advhH, HALF_H, aoWt, adv_out_b, adv, ADV_N);

    final_k<<<BQ, 256>>>(val, adv, out);
    (void)in_sizes; (void)n_in; (void)out_size;
}

// round 9
// speedup vs baseline: 1.6753x; 1.0456x over previous
#include <cuda_runtime.h>
#include <cuda_fp16.h>
#include <math.h>
#include <stdint.h>

// ---------------------------------------------------------------------------
// RainbowNet fused inference — fp16 warp-MMA + ldmatrix, BK=64 2-stage.
// Attention folded (cls query is batch-independent):
//   scores[h,j] = x_j . wscore_h + c_h ;  pooled = XW @ Mflat + c_pool
// GEMMs: mma.sync.m16n8k16 f16 (fp32 accum), ldmatrix.x4 fragment loads,
// BK=64 double-buffered cp.async (R7 delta vs R6's BK=32 3-stage).
// ---------------------------------------------------------------------------

constexpr int BQ       = 8192;
constexpr int STATE_SZ = 1360;
constexpr int KPAD0    = 1536;   // 1488 padded to multiple of 64
constexpr int TRUNK_H  = 1024;
constexpr int HALF_H   = 512;
constexpr int ATOMS    = 51;
constexpr int ACTIONS  = 81;
constexpr int ADV_N    = ACTIONS * ATOMS;  // 4131

constexpr size_t al256(size_t x) { return (x + 255) & ~(size_t)255; }
constexpr size_t B_STATEH = 0;
constexpr size_t B_XWH   = al256(B_STATEH + (size_t)BQ * KPAD0 * 2);
constexpr size_t B_Z0    = al256(B_XWH   + (size_t)BQ * 512 * 2);
constexpr size_t B_Z0H   = al256(B_Z0    + (size_t)BQ * 1024 * 4);
constexpr size_t B_H1    = al256(B_Z0H   + (size_t)BQ * 1024 * 2);
constexpr size_t B_H1H   = al256(B_H1    + (size_t)BQ * 1024 * 4);
constexpr size_t B_VALHH = al256(B_H1H   + (size_t)BQ * 1024 * 2);
constexpr size_t B_ADVHH = al256(B_VALHH + (size_t)BQ * 512 * 2);
constexpr size_t B_VAL   = al256(B_ADVHH + (size_t)BQ * 512 * 2);
constexpr size_t B_ADV   = al256(B_VAL   + (size_t)BQ * ATOMS * 4);
constexpr size_t B_T0W   = al256(B_ADV   + (size_t)BQ * ADV_N * 4);
constexpr size_t B_T1W   = al256(B_T0W   + (size_t)1024 * KPAD0 * 2);
constexpr size_t B_VFCW  = al256(B_T1W   + (size_t)1024 * 1024 * 2);
constexpr size_t B_AFCW  = al256(B_VFCW  + (size_t)512 * 1024 * 2);
constexpr size_t B_VOW   = al256(B_AFCW  + (size_t)512 * 1024 * 2);
constexpr size_t B_AOW   = al256(B_VOW   + (size_t)ATOMS * 512 * 2);
constexpr size_t B_MT    = al256(B_AOW   + (size_t)ADV_N * 512 * 2);
constexpr size_t B_QVEC  = al256(B_MT    + (size_t)128 * 512 * 2);
constexpr size_t B_WS    = al256(B_QVEC  + 512);
constexpr size_t B_CS    = al256(B_WS    + 2048);
constexpr size_t B_CP    = al256(B_CS    + 64);
constexpr size_t B_TOTAL = al256(B_CP    + 512);

__device__ __align__(256) unsigned char g_bytes[B_TOTAL];

__device__ __forceinline__ float wsum(float v) {
#pragma unroll
    for (int o = 16; o > 0; o >>= 1) v += __shfl_xor_sync(0xffffffffu, v, o);
    return v;
}
__device__ __forceinline__ float wmax(float v) {
#pragma unroll
    for (int o = 16; o > 0; o >>= 1) v = fmaxf(v, __shfl_xor_sync(0xffffffffu, v, o));
    return v;
}

// ---------------------------------------------------------------------------
// prep_small: qvec, wscore, cscore, cpool   (1 block, 128 threads)
// ---------------------------------------------------------------------------
__global__ void prep_small(const float* __restrict__ cls,
                           const float* __restrict__ ipW,
                           const float* __restrict__ ipB,
                           const float* __restrict__ opW,
                           const float* __restrict__ opB)
{
    int tid = threadIdx.x;
    float* qvec   = (float*)(g_bytes + B_QVEC);
    float* wscore = (float*)(g_bytes + B_WS);
    float* cscore = (float*)(g_bytes + B_CS);
    float* cpool  = (float*)(g_bytes + B_CP);

    {
        float q = ipB[tid];
        const float* wrow = ipW + (size_t)tid * 128;
        for (int d = 0; d < 128; d++) q += cls[d] * wrow[d];
        qvec[tid] = q;
    }
    __syncthreads();

    const float rs = 0.17677669529663687f;
    for (int idx = tid; idx < 512; idx += 128) {
        int h = idx >> 7, d = idx & 127;
        float s = 0.f;
        for (int e = 0; e < 32; e++)
            s += qvec[h * 32 + e] * ipW[(size_t)(128 + h * 32 + e) * 128 + d];
        wscore[idx] = s * rs;
    }
    if (tid < 4) {
        float s = 0.f;
        for (int e = 0; e < 32; e++)
            s += qvec[tid * 32 + e] * ipB[128 + tid * 32 + e];
        cscore[tid] = s * rs;
    }
    {
        float c = opB[tid];
        const float* orow = opW + (size_t)tid * 128;
        for (int e = 0; e < 128; e++) c += orow[e] * ipB[256 + e];
        cpool[tid] = c;
    }
}

// Mt[d][k] (N-major fp16, 128x512)
__global__ void prep_M(const float* __restrict__ ipW, const float* __restrict__ opW)
{
    int idx = blockIdx.x * blockDim.x + threadIdx.x;
    if (idx >= 512 * 128) return;
    int d = idx & 127;
    int k = idx >> 7;
    int h = k >> 7;
    int c = k & 127;
    float s = 0.f;
    for (int e = 0; e < 32; e++)
        s += ipW[(size_t)(256 + h * 32 + e) * 128 + c] * opW[(size_t)d * 128 + h * 32 + e];
    ((__half*)(g_bytes + B_MT))[(size_t)d * 512 + k] = __float2half(s);
}

// ---------------------------------------------------------------------------
// weight transpose+convert: W (K x N fp32) -> Wt (N x Kpad fp16), zero-pad k
// ---------------------------------------------------------------------------
__global__ void convT(const float* __restrict__ W, __half* __restrict__ Wt,
                      int K, int N, int Kpad)
{
    __shared__ float tile[32][33];
    int k0 = blockIdx.y * 32, n0 = blockIdx.x * 32;
    int tx = threadIdx.x, ty = threadIdx.y;  // 32 x 8
#pragma unroll
    for (int i = 0; i < 4; i++) {
        int k = k0 + ty + 8 * i, n = n0 + tx;
        tile[ty + 8 * i][tx] = (k < K && n < N) ? W[(size_t)k * N + n] : 0.f;
    }
    __syncthreads();
#pragma unroll
    for (int i = 0; i < 4; i++) {
        int n = n0 + ty + 8 * i, k = k0 + tx;
        if (n < N && k < Kpad)
            Wt[(size_t)n * Kpad + k] = __float2half(tile[tx][ty + 8 * i]);
    }
}

__global__ void conv_state(const float* __restrict__ state)
{
    int b = blockIdx.x;
    const float* src = state + (size_t)b * STATE_SZ;
    __half* dst = (__half*)(g_bytes + B_STATEH) + (size_t)b * KPAD0;
    for (int k = threadIdx.x; k < KPAD0; k += 256)
        dst[k] = (k < STATE_SZ) ? __float2half(src[k]) : __float2half(0.f);
}

// ---------------------------------------------------------------------------
// attention kernel: one block per batch item, 128 threads (4 warps)
// ---------------------------------------------------------------------------
__device__ __forceinline__ void slot_info(int s, int& cat, int& off) {
    const int defs[9] = {16, 8, 4, 4, 4, 8, 8, 8, 8};
    int base = 59, acc = 0;
#pragma unroll
    for (int c = 0; c < 9; c++) {
        if (s < acc + defs[c]) { cat = c; off = base + 1 + (s - acc) * 4; return; }
        acc += defs[c];
        base += 1 + defs[c] * 4;
    }
    cat = 8; off = 0;
}

__global__ __launch_bounds__(128)
void attn_k(const float* __restrict__ state,
            const float* __restrict__ embW, const float* __restrict__ embB,
            const float* __restrict__ lng,  const float* __restrict__ lnb,
            const float* __restrict__ cls)
{
    int b = blockIdx.x;
    int tid = threadIdx.x;
    int lane = tid & 31, warp = tid >> 5;

    __shared__ float xs[69][128];
    __shared__ float tokf[68][8];
    __shared__ float sc[4][72];
    __shared__ int s_any;

    const float* st = state + (size_t)b * STATE_SZ;
    float presv = 0.f;
    if (tid < 68) {
        int cat, off;
        slot_info(tid, cat, off);
        float p   = st[1020 + off + 0];
        float dx  = st[1020 + off + 1];
        float dy  = st[1020 + off + 2];
        float di  = st[1020 + off + 3];
        float pp  = st[680 + off + 0];
        float pdx = st[680 + off + 1];
        float pdy = st[680 + off + 2];
        float vv  = (p > 0.5f && pp > 0.5f) ? 1.f : 0.f;
        tokf[tid][0] = dx;
        tokf[tid][1] = dy;
        tokf[tid][2] = di;
        tokf[tid][3] = (dx - pdx) * vv;
        tokf[tid][4] = (dy - pdy) * vv;
        tokf[tid][5] = (float)cat * 0.125f;
        tokf[tid][6] = p;
        presv = p;
    }
    if (tid == 127) s_any = 0;
    __syncthreads();
    if (tid < 68 && presv >= 0.5f) atomicOr(&s_any, 1);
    __syncthreads();
    int all_empty = (s_any == 0);

    const float* wsc = (const float*)(g_bytes + B_WS);
    const float* csc = (const float*)(g_bytes + B_CS);

    for (int j = warp; j < 69; j += 4) {
        float xv[4];
        if (j == 0) {
#pragma unroll
            for (int q = 0; q < 4; q++) xv[q] = cls[lane + 32 * q];
        } else {
            const float* tf = tokf[j - 1];
            float f0 = tf[0], f1 = tf[1], f2 = tf[2], f3 = tf[3], f4 = tf[4], f5 = tf[5], f6 = tf[6];
#pragma unroll
            for (int q = 0; q < 4; q++) {
                int d = lane + 32 * q;
                float e = embB[d];
                e += f0 * embW[0 * 128 + d];
                e += f1 * embW[1 * 128 + d];
                e += f2 * embW[2 * 128 + d];
                e += f3 * embW[3 * 128 + d];
                e += f4 * embW[4 * 128 + d];
                e += f5 * embW[5 * 128 + d];
                e += f6 * embW[6 * 128 + d];
                xv[q] = e;
            }
            float s = xv[0] + xv[1] + xv[2] + xv[3];
            float ss = xv[0]*xv[0] + xv[1]*xv[1] + xv[2]*xv[2] + xv[3]*xv[3];
            s = wsum(s); ss = wsum(ss);
            float mean = s * (1.f / 128.f);
            float var  = ss * (1.f / 128.f) - mean * mean;
            float inv  = rsqrtf(var + 1e-5f);
#pragma unroll
            for (int q = 0; q < 4; q++) {
                int d = lane + 32 * q;
                xv[q] = (xv[q] - mean) * inv * lng[d] + lnb[d];
            }
        }
#pragma unroll
        for (int q = 0; q < 4; q++) xs[j][lane + 32 * q] = xv[q];

        float s0 = 0, s1 = 0, s2 = 0, s3 = 0;
#pragma unroll
        for (int q = 0; q < 4; q++) {
            int d = lane + 32 * q;
            float x = xv[q];
            s0 += x * wsc[d];
            s1 += x * wsc[128 + d];
            s2 += x * wsc[256 + d];
            s3 += x * wsc[384 + d];
        }
        s0 = wsum(s0); s1 = wsum(s1); s2 = wsum(s2); s3 = wsum(s3);
        if (lane == 0) {
            bool masked = (j > 0) && (tokf[j - 1][6] < 0.5f) && !all_empty;
            sc[0][j] = masked ? -1e9f : s0 + csc[0];
            sc[1][j] = masked ? -1e9f : s1 + csc[1];
            sc[2][j] = masked ? -1e9f : s2 + csc[2];
            sc[3][j] = masked ? -1e9f : s3 + csc[3];
        }
    }
    __syncthreads();

    {
        int h = warp;
        float v0 = (lane < 69)      ? sc[h][lane]      : -1e30f;
        float v1 = (lane + 32 < 69) ? sc[h][lane + 32] : -1e30f;
        float v2 = (lane + 64 < 69) ? sc[h][lane + 64] : -1e30f;
        float m = wmax(fmaxf(fmaxf(v0, v1), v2));
        float e0 = (lane < 69)      ? expf(v0 - m) : 0.f;
        float e1 = (lane + 32 < 69) ? expf(v1 - m) : 0.f;
        float e2 = (lane + 64 < 69) ? expf(v2 - m) : 0.f;
        float s = wsum(e0 + e1 + e2);
        float inv = 1.f / s;
        if (lane < 69)      sc[h][lane]      = e0 * inv;
        if (lane + 32 < 69) sc[h][lane + 32] = e1 * inv;
        if (lane + 64 < 69) sc[h][lane + 64] = e2 * inv;
    }
    __syncthreads();

    {
        int d = tid;
        float a0 = 0, a1 = 0, a2 = 0, a3 = 0;
        for (int j = 0; j < 69; j++) {
            float x = xs[j][d];
            a0 += sc[0][j] * x;
            a1 += sc[1][j] * x;
            a2 += sc[2][j] * x;
            a3 += sc[3][j] * x;
        }
        __half* xw = (__half*)(g_bytes + B_XWH) + (size_t)b * 512;
        xw[d]       = __float2half(a0);
        xw[128 + d] = __float2half(a1);
        xw[256 + d] = __float2half(a2);
        xw[384 + d] = __float2half(a3);
    }
}

// ---------------------------------------------------------------------------
// fp16 tensor-core GEMM, ldmatrix + BK=64 2-stage cp.async.
//   C(MxN) = A(MxK fp16 rowmaj, lda) @ Bt(N x K fp16 N-major)^T + bias [+relu]
//   BM=BN=128, BK=64; 256 threads (8 warps, 2x4 of 64x32 warp tiles);
//   smem row stride 72 halves (144B) — LDSM bank-conflict-free.
// ---------------------------------------------------------------------------
constexpr int GSMEM = 2 * 2 * 128 * 72 * 2;  // 73728 bytes

template <bool OUTH, int ACT, bool NGUARD>
__global__ __launch_bounds__(256, 2)
void gemm_f16(int M, int N, int K,
              const __half* __restrict__ A, int lda,
              const __half* __restrict__ Bt,
              const float* __restrict__ bias,
              void* __restrict__ Cv, int ldc)
{
    constexpr int LDS_ = 72;                 // halves per smem row
    constexpr int ROWB = LDS_ * 2;           // 144 bytes per row
    extern __shared__ __half sm[];
    __half* Asm = sm;                     // [2][128][72]
    __half* Bsm = sm + 2 * 128 * LDS_;    // [2][128][72]

    int tid = threadIdx.x, lane = tid & 31, warp = tid >> 5;
    int wm = (warp >> 2) * 64, wn = (warp & 3) * 32;
    int bm = blockIdx.y * 128, bn = blockIdx.x * 128;
    int g = lane >> 2, tg = lane & 3;        // epilogue mapping
    int lg = lane >> 3, lr = lane & 7;       // ldmatrix lane groups

    uint32_t aBase, bBase;
    {
        uint64_t t = (uint64_t)__cvta_generic_to_shared(Asm);
        aBase = (uint32_t)t;
        t = (uint64_t)__cvta_generic_to_shared(Bsm);
        bBase = (uint32_t)t;
    }
    // A x4 tiles: (m0-7,k0),(m8-15,k0),(m0-7,k8),(m8-15,k8)
    uint32_t aOffL = (uint32_t)((wm + (lg & 1) * 8 + lr) * ROWB + (lg >> 1) * 16);
    // B x4 tiles: (n0-7,k0),(n0-7,k8),(n8-15,k0),(n8-15,k8)
    uint32_t bOffL = (uint32_t)((wn + (lg >> 1) * 8 + lr) * ROWB + (lg & 1) * 16);

    float acc[4][4][4];
#pragma unroll
    for (int i = 0; i < 4; i++)
#pragma unroll
        for (int j = 0; j < 4; j++)
#pragma unroll
            for (int c = 0; c < 4; c++) acc[i][j][c] = 0.f;

    auto issue = [&](int t, int s) {
        int k0 = t * 64;
#pragma unroll
        for (int i = 0; i < 4; i++) {
            int q = tid + 256 * i;
            int r = q >> 3, j = q & 7;
            const __half* src = A + (size_t)(bm + r) * lda + k0 + j * 8;
            uint32_t dst = (uint32_t)__cvta_generic_to_shared(
                Asm + ((size_t)s * 128 + r) * LDS_ + j * 8);
            asm volatile("cp.async.cg.shared.global [%0], [%1], 16;\n"
                         :: "r"(dst), "l"(src));
        }
#pragma unroll
        for (int i = 0; i < 4; i++) {
            int q = tid + 256 * i;
            int r = q >> 3, j = q & 7;
            int gn = bn + r;
            uint32_t dst = (uint32_t)__cvta_generic_to_shared(
                Bsm + ((size_t)s * 128 + r) * LDS_ + j * 8);
            if (NGUARD) {
                int cn = gn < N ? gn : N - 1;
                const __half* src = Bt + (size_t)cn * K + k0 + j * 8;
                int sz = gn < N ? 16 : 0;
                asm volatile("cp.async.cg.shared.global [%0], [%1], 16, %2;\n"
                             :: "r"(dst), "l"(src), "r"(sz));
            } else {
                const __half* src = Bt + (size_t)gn * K + k0 + j * 8;
                asm volatile("cp.async.cg.shared.global [%0], [%1], 16;\n"
                             :: "r"(dst), "l"(src));
            }
        }
        asm volatile("cp.async.commit_group;\n");
    };

    int NT = K / 64;
    issue(0, 0);
    asm volatile("cp.async.wait_group 0;\n");
    __syncthreads();

    for (int t = 0; t < NT; t++) {
        int s = t & 1;
        if (t + 1 < NT) issue(t + 1, s ^ 1);

        uint32_t aS = aBase + (uint32_t)(s * 128 * ROWB);
        uint32_t bS = bBase + (uint32_t)(s * 128 * ROWB);
#pragma unroll
        for (int kk = 0; kk < 4; kk++) {
            uint32_t kby = (uint32_t)(kk * 32);  // 16 halves per step
            uint32_t a[4][4];
#pragma unroll
            for (int i = 0; i < 4; i++) {
                uint32_t addr = aS + aOffL + (uint32_t)(i * 16 * ROWB) + kby;
                asm volatile(
                    "ldmatrix.sync.aligned.m8n8.x4.shared.b16 {%0,%1,%2,%3}, [%4];"
                    : "=r"(a[i][0]), "=r"(a[i][1]), "=r"(a[i][2]), "=r"(a[i][3])
                    : "r"(addr));
            }
            uint32_t bf[4][2];
#pragma unroll
            for (int j2 = 0; j2 < 2; j2++) {
                uint32_t addr = bS + bOffL + (uint32_t)(j2 * 16 * ROWB) + kby;
                asm volatile(
                    "ldmatrix.sync.aligned.m8n8.x4.shared.b16 {%0,%1,%2,%3}, [%4];"
                    : "=r"(bf[2 * j2][0]), "=r"(bf[2 * j2][1]),
                      "=r"(bf[2 * j2 + 1][0]), "=r"(bf[2 * j2 + 1][1])
                    : "r"(addr));
            }
#pragma unroll
            for (int i = 0; i < 4; i++)
#pragma unroll
                for (int j = 0; j < 4; j++) {
                    asm volatile(
                        "mma.sync.aligned.m16n8k16.row.col.f32.f16.f16.f32 "
                        "{%0,%1,%2,%3},{%4,%5,%6,%7},{%8,%9},{%0,%1,%2,%3};"
                        : "+f"(acc[i][j][0]), "+f"(acc[i][j][1]),
                          "+f"(acc[i][j][2]), "+f"(acc[i][j][3])
                        : "r"(a[i][0]), "r"(a[i][1]), "r"(a[i][2]), "r"(a[i][3]),
                          "r"(bf[j][0]), "r"(bf[j][1]));
                }
        }
        if (t + 1 < NT) asm volatile("cp.async.wait_group 0;\n");
        __syncthreads();
    }

    // epilogue
    __half* Ch = (__half*)Cv;
    float*  Cf = (float*)Cv;
#pragma unroll
    for (int i = 0; i < 4; i++) {
        int r0 = bm + wm + 16 * i + g;
#pragma unroll
        for (int j = 0; j < 4; j++) {
            int c = bn + wn + 8 * j + 2 * tg;
#pragma unroll
            for (int h = 0; h < 2; h++) {
                int r = r0 + 8 * h;
                float v0 = acc[i][j][2 * h + 0];
                float v1 = acc[i][j][2 * h + 1];
                if (NGUARD) {
                    if (c < N) {
                        float v = v0 + bias[c];
                        if (ACT == 1) v = fmaxf(v, 0.f);
                        if (OUTH) Ch[(size_t)r * ldc + c] = __float2half(v);
                        else      Cf[(size_t)r * ldc + c] = v;
                    }
                    if (c + 1 < N) {
                        float v = v1 + bias[c + 1];
                        if (ACT == 1) v = fmaxf(v, 0.f);
                        if (OUTH) Ch[(size_t)r * ldc + c + 1] = __float2half(v);
                        else      Cf[(size_t)r * ldc + c + 1] = v;
                    }
                } else {
                    float v0b = v0 + bias[c];
                    float v1b = v1 + bias[c + 1];
                    if (ACT == 1) { v0b = fmaxf(v0b, 0.f); v1b = fmaxf(v1b, 0.f); }
                    if (OUTH) {
                        *(__half2*)(Ch + (size_t)r * ldc + c) =
                            __halves2half2(__float2half(v0b), __float2half(v1b));
                    } else {
                        *(float2*)(Cf + (size_t)r * ldc + c) = make_float2(v0b, v1b);
                    }
                }
            }
        }
    }
}

// ---------------------------------------------------------------------------
// rowwise layernorm + relu: fp32 in -> fp16 out, one block per row
// ---------------------------------------------------------------------------
__global__ void ln_relu_k(const float* __restrict__ x, __half* __restrict__ y,
                          const float* __restrict__ g, const float* __restrict__ bta,
                          int L)
{
    size_t row = blockIdx.x;
    const float* p = x + row * (size_t)L;
    __half* q = y + row * (size_t)L;
    int tid = threadIdx.x;
    float s = 0.f, ss = 0.f;
    for (int i = tid; i < L; i += 256) {
        float v = p[i];
        s += v; ss += v * v;
    }
    __shared__ float sh1[8], sh2[8];
    s = wsum(s); ss = wsum(ss);
    int w = tid >> 5, l = tid & 31;
    if (l == 0) { sh1[w] = s; sh2[w] = ss; }
    __syncthreads();
    if (w == 0) {
        float a = (l < 8) ? sh1[l] : 0.f;
        float c = (l < 8) ? sh2[l] : 0.f;
        a = wsum(a); c = wsum(c);
        if (l == 0) { sh1[0] = a; sh2[0] = c; }
    }
    __syncthreads();
    float mean = sh1[0] / (float)L;
    float var  = sh2[0] / (float)L - mean * mean;
    float inv  = rsqrtf(var + 1e-5f);
    for (int i = tid; i < L; i += 256) {
        float v = p[i];
        q[i] = __float2half(fmaxf((v - mean) * inv * g[i] + bta[i], 0.f));
    }
}

// ---------------------------------------------------------------------------
// final dueling head + softmax over atoms; one block per batch item
// ---------------------------------------------------------------------------
__global__ __launch_bounds__(256)
void final_k(const float* __restrict__ valg, const float* __restrict__ advg,
             float* __restrict__ out)
{
    int b = blockIdx.x;
    int tid = threadIdx.x;
    __shared__ float sadv[ADV_N];
    __shared__ float cm[ATOMS];
    __shared__ float sval[ATOMS];
    const float* ap = advg + (size_t)b * ADV_N;
    const float* vp = valg + (size_t)b * ATOMS;
    for (int i = tid; i < ADV_N; i += 256) sadv[i] = ap[i];
    if (tid < ATOMS) sval[tid] = vp[tid];
    __syncthreads();
    if (tid < ATOMS) {
        float s = 0.f;
#pragma unroll
        for (int a = 0; a < ACTIONS; a++) s += sadv[a * ATOMS + tid];
        cm[tid] = s * (1.f / 81.f);
    }
    __syncthreads();
    int w = tid >> 5, l = tid & 31;
    float* op = out + (size_t)b * ADV_N;
    for (int a = w; a < ACTIONS; a += 8) {
        float q0 = (l < ATOMS)      ? sval[l]      + sadv[a * ATOMS + l]      - cm[l]      : -1e30f;
        float q1 = (l + 32 < ATOMS) ? sval[l + 32] + sadv[a * ATOMS + l + 32] - cm[l + 32] : -1e30f;
        float m = wmax(fmaxf(q0, q1));
        float e0 = (l < ATOMS)      ? expf(q0 - m) : 0.f;
        float e1 = (l + 32 < ATOMS) ? expf(q1 - m) : 0.f;
        float sm2 = wsum(e0 + e1);
        float inv = 1.f / sm2;
        if (l < ATOMS)      op[a * ATOMS + l]      = e0 * inv;
        if (l + 32 < ATOMS) op[a * ATOMS + l + 32] = e1 * inv;
    }
}

// ---------------------------------------------------------------------------
extern "C" void kernel_launch(void* const* d_in, const int* in_sizes, int n_in,
                              void* d_out, int out_size)
{
    const float* state     = (const float*)d_in[0];
    const float* embed_W   = (const float*)d_in[1];
    const float* embed_b   = (const float*)d_in[2];
    const float* ln_g      = (const float*)d_in[3];
    const float* ln_b      = (const float*)d_in[4];
    const float* cls_tok   = (const float*)d_in[5];
    const float* in_proj_W = (const float*)d_in[6];
    const float* in_proj_b = (const float*)d_in[7];
    const float* out_proj_W= (const float*)d_in[8];
    const float* out_proj_b= (const float*)d_in[9];
    const float* t0_W      = (const float*)d_in[10];
    const float* t0_b      = (const float*)d_in[11];
    const float* t0_g      = (const float*)d_in[12];
    const float* t0_beta   = (const float*)d_in[13];
    const float* t1_W      = (const float*)d_in[14];
    const float* t1_b      = (const float*)d_in[15];
    const float* t1_g      = (const float*)d_in[16];
    const float* t1_beta   = (const float*)d_in[17];
    const float* val_fc_W  = (const float*)d_in[18];
    const float* val_fc_b  = (const float*)d_in[19];
    const float* val_out_W = (const float*)d_in[20];
    const float* val_out_b = (const float*)d_in[21];
    const float* adv_fc_W  = (const float*)d_in[22];
    const float* adv_fc_b  = (const float*)d_in[23];
    const float* adv_out_W = (const float*)d_in[24];
    const float* adv_out_b = (const float*)d_in[25];
    float* out = (float*)d_out;

    unsigned char* base = nullptr;
    cudaGetSymbolAddress((void**)&base, g_bytes);
    __half* stateH = (__half*)(base + B_STATEH);
    __half* xwH    = (__half*)(base + B_XWH);
    float*  z0     = (float*)(base + B_Z0);
    __half* z0H    = (__half*)(base + B_Z0H);
    float*  h1     = (float*)(base + B_H1);
    __half* h1H    = (__half*)(base + B_H1H);
    __half* valhH  = (__half*)(base + B_VALHH);
    __half* advhH  = (__half*)(base + B_ADVHH);
    float*  val    = (float*)(base + B_VAL);
    float*  adv    = (float*)(base + B_ADV);
    __half* t0Wt   = (__half*)(base + B_T0W);
    __half* t1Wt   = (__half*)(base + B_T1W);
    __half* vfcWt  = (__half*)(base + B_VFCW);
    __half* afcWt  = (__half*)(base + B_AFCW);
    __half* voWt   = (__half*)(base + B_VOW);
    __half* aoWt   = (__half*)(base + B_AOW);
    __half* Mt     = (__half*)(base + B_MT);
    float*  cpool  = (float*)(base + B_CP);

    cudaFuncSetAttribute(gemm_f16<true, 0, false>,
                         cudaFuncAttributeMaxDynamicSharedMemorySize, GSMEM);
    cudaFuncSetAttribute(gemm_f16<false, 0, false>,
                         cudaFuncAttributeMaxDynamicSharedMemorySize, GSMEM);
    cudaFuncSetAttribute(gemm_f16<true, 1, false>,
                         cudaFuncAttributeMaxDynamicSharedMemorySize, GSMEM);
    cudaFuncSetAttribute(gemm_f16<false, 0, true>,
                         cudaFuncAttributeMaxDynamicSharedMemorySize, GSMEM);

    dim3 t32x8(32, 8);
    conv_state<<<BQ, 256>>>(state);
    convT<<<dim3(32, 48), t32x8>>>(t0_W, t0Wt, 1488, 1024, KPAD0);
    convT<<<dim3(32, 32), t32x8>>>(t1_W, t1Wt, 1024, 1024, 1024);
    convT<<<dim3(16, 32), t32x8>>>(val_fc_W, vfcWt, 1024, 512, 1024);
    convT<<<dim3(16, 32), t32x8>>>(adv_fc_W, afcWt, 1024, 512, 1024);
    convT<<<dim3(2, 16),  t32x8>>>(val_out_W, voWt, 512, ATOMS, 512);
    convT<<<dim3(130, 16), t32x8>>>(adv_out_W, aoWt, 512, ADV_N, 512);

    prep_small<<<1, 128>>>(cls_tok, in_proj_W, in_proj_b, out_proj_W, out_proj_b);
    prep_M<<<256, 256>>>(in_proj_W, out_proj_W);

    attn_k<<<BQ, 128>>>(state, embed_W, embed_b, ln_g, ln_b, cls_tok);

    // pooled (fp16) -> stateH cols 1360..1487
    gemm_f16<true, 0, false><<<dim3(1, 64), 256, GSMEM>>>(
        BQ, 128, 512, xwH, 512, Mt, cpool, stateH + 1360, KPAD0);

    // trunk 0
    gemm_f16<false, 0, false><<<dim3(8, 64), 256, GSMEM>>>(
        BQ, TRUNK_H, KPAD0, stateH, KPAD0, t0Wt, t0_b, z0, TRUNK_H);
    ln_relu_k<<<BQ, 256>>>(z0, z0H, t0_g, t0_beta, TRUNK_H);

    // trunk 1
    gemm_f16<false, 0, false><<<dim3(8, 64), 256, GSMEM>>>(
        BQ, TRUNK_H, TRUNK_H, z0H, TRUNK_H, t1Wt, t1_b, h1, TRUNK_H);
    ln_relu_k<<<BQ, 256>>>(h1, h1H, t1_g, t1_beta, TRUNK_H);

    // heads (relu fused, fp16 out)
    gemm_f16<true, 1, false><<<dim3(4, 64), 256, GSMEM>>>(
        BQ, HALF_H, TRUNK_H, h1H, TRUNK_H, vfcWt, val_fc_b, valhH, HALF_H);
    gemm_f16<true, 1, false><<<dim3(4, 64), 256, GSMEM>>>(
        BQ, HALF_H, TRUNK_H, h1H, TRUNK_H, afcWt, adv_fc_b, advhH, HALF_H);

    gemm_f16<false, 0, true><<<dim3(1, 64), 256, GSMEM>>>(
        BQ, ATOMS, HALF_H, valhH, HALF_H, voWt, val_out_b, val, ATOMS);
    gemm_f16<false, 0, true><<<dim3(33, 64), 256, GSMEM>>>(
        BQ, ADV_N, HALF_H, advhH, HALF_H, aoWt, adv_out_b, adv, ADV_N);

    final_k<<<BQ, 256>>>(val, adv, out);
    (void)in_sizes; (void)n_in; (void)out_size;
}

// round 10
// speedup vs baseline: 1.6974x; 1.0132x over previous
#include <cuda_runtime.h>
#include <cuda_fp16.h>
#include <math.h>
#include <stdint.h>

// ---------------------------------------------------------------------------
// RainbowNet fused inference — fp16 warp-MMA + ldmatrix, BK=64 2-stage,
// fused dueling-softmax adv GEMM (R9).
//   scores[h,j] = x_j . wscore_h + c_h ;  pooled = XW @ Mflat + c_pool
//   cm[atom] = advh @ mean_a(W) + mean_a(b)  (precomputed mean weights)
//   out = softmax_atoms(adv + val - cm)  fused into the adv GEMM epilogue.
// ---------------------------------------------------------------------------

constexpr int BQ       = 8192;
constexpr int STATE_SZ = 1360;
constexpr int KPAD0    = 1536;   // 1488 padded to multiple of 64
constexpr int TRUNK_H  = 1024;
constexpr int HALF_H   = 512;
constexpr int ATOMS    = 51;
constexpr int ACTIONS  = 81;
constexpr int ADV_N    = ACTIONS * ATOMS;  // 4131

constexpr size_t al256(size_t x) { return (x + 255) & ~(size_t)255; }
constexpr size_t B_STATEH = 0;
constexpr size_t B_XWH   = al256(B_STATEH + (size_t)BQ * KPAD0 * 2);
constexpr size_t B_Z0    = al256(B_XWH   + (size_t)BQ * 512 * 2);
constexpr size_t B_Z0H   = al256(B_Z0    + (size_t)BQ * 1024 * 4);
constexpr size_t B_H1    = al256(B_Z0H   + (size_t)BQ * 1024 * 2);
constexpr size_t B_H1H   = al256(B_H1    + (size_t)BQ * 1024 * 4);
constexpr size_t B_COMBH = al256(B_H1H   + (size_t)BQ * 1024 * 2);  // 8192x1024 h (val|adv)
constexpr size_t B_VAL   = al256(B_COMBH + (size_t)BQ * 1024 * 2);
constexpr size_t B_CMV   = al256(B_VAL   + (size_t)BQ * ATOMS * 4);
constexpr size_t B_T0W   = al256(B_CMV   + (size_t)BQ * ATOMS * 4);
constexpr size_t B_T1W   = al256(B_T0W   + (size_t)1024 * KPAD0 * 2);
constexpr size_t B_VFCW  = al256(B_T1W   + (size_t)1024 * 1024 * 2);
constexpr size_t B_AFCW  = al256(B_VFCW  + (size_t)512 * 1024 * 2);  // contiguous after VFCW
constexpr size_t B_VOW   = al256(B_AFCW  + (size_t)512 * 1024 * 2);
constexpr size_t B_AOW   = al256(B_VOW   + (size_t)ATOMS * 512 * 2);
constexpr size_t B_MT    = al256(B_AOW   + (size_t)ADV_N * 512 * 2);
constexpr size_t B_QVEC  = al256(B_MT    + (size_t)128 * 512 * 2);
constexpr size_t B_WS    = al256(B_QVEC  + 512);
constexpr size_t B_CS    = al256(B_WS    + 2048);
constexpr size_t B_CP    = al256(B_CS    + 64);
constexpr size_t B_FCB   = al256(B_CP    + 512);                      // 1024 f
constexpr size_t B_WM    = al256(B_FCB   + 4096);                     // 51x512 h
constexpr size_t B_BM    = al256(B_WM    + (size_t)ATOMS * 512 * 2);  // 51 f
constexpr size_t B_TOTAL = al256(B_BM    + 256);

__device__ __align__(256) unsigned char g_bytes[B_TOTAL];

__device__ __forceinline__ float wsum(float v) {
#pragma unroll
    for (int o = 16; o > 0; o >>= 1) v += __shfl_xor_sync(0xffffffffu, v, o);
    return v;
}
__device__ __forceinline__ float wmax(float v) {
#pragma unroll
    for (int o = 16; o > 0; o >>= 1) v = fmaxf(v, __shfl_xor_sync(0xffffffffu, v, o));
    return v;
}

// ---------------------------------------------------------------------------
// prep kernels
// ---------------------------------------------------------------------------
__global__ void prep_small(const float* __restrict__ cls,
                           const float* __restrict__ ipW,
                           const float* __restrict__ ipB,
                           const float* __restrict__ opW,
                           const float* __restrict__ opB)
{
    int tid = threadIdx.x;
    float* qvec   = (float*)(g_bytes + B_QVEC);
    float* wscore = (float*)(g_bytes + B_WS);
    float* cscore = (float*)(g_bytes + B_CS);
    float* cpool  = (float*)(g_bytes + B_CP);

    {
        float q = ipB[tid];
        const float* wrow = ipW + (size_t)tid * 128;
        for (int d = 0; d < 128; d++) q += cls[d] * wrow[d];
        qvec[tid] = q;
    }
    __syncthreads();

    const float rs = 0.17677669529663687f;
    for (int idx = tid; idx < 512; idx += 128) {
        int h = idx >> 7, d = idx & 127;
        float s = 0.f;
        for (int e = 0; e < 32; e++)
            s += qvec[h * 32 + e] * ipW[(size_t)(128 + h * 32 + e) * 128 + d];
        wscore[idx] = s * rs;
    }
    if (tid < 4) {
        float s = 0.f;
        for (int e = 0; e < 32; e++)
            s += qvec[tid * 32 + e] * ipB[128 + tid * 32 + e];
        cscore[tid] = s * rs;
    }
    {
        float c = opB[tid];
        const float* orow = opW + (size_t)tid * 128;
        for (int e = 0; e < 128; e++) c += orow[e] * ipB[256 + e];
        cpool[tid] = c;
    }
}

__global__ void prep_M(const float* __restrict__ ipW, const float* __restrict__ opW)
{
    int idx = blockIdx.x * blockDim.x + threadIdx.x;
    if (idx >= 512 * 128) return;
    int d = idx & 127;
    int k = idx >> 7;
    int h = k >> 7;
    int c = k & 127;
    float s = 0.f;
    for (int e = 0; e < 32; e++)
        s += ipW[(size_t)(256 + h * 32 + e) * 128 + c] * opW[(size_t)d * 128 + h * 32 + e];
    ((__half*)(g_bytes + B_MT))[(size_t)d * 512 + k] = __float2half(s);
}

// concat bias for combined fc GEMM
__global__ void prep_fcb(const float* __restrict__ vb, const float* __restrict__ ab)
{
    int i = blockIdx.x * 256 + threadIdx.x;
    float* fcb = (float*)(g_bytes + B_FCB);
    if (i < 512) fcb[i] = vb[i];
    else if (i < 1024) fcb[i] = ab[i - 512];
}

// mean-over-actions weights: Wm[n][k] = mean_a adv_out_W[k][a*51+n]; bm likewise
__global__ void prep_wm(const float* __restrict__ W, const float* __restrict__ b)
{
    int idx = blockIdx.x * 256 + threadIdx.x;
    if (idx >= ATOMS * 512) return;
    int n = idx / 512, k = idx % 512;
    float s = 0.f;
    for (int a = 0; a < ACTIONS; a++)
        s += W[(size_t)k * ADV_N + a * ATOMS + n];
    ((__half*)(g_bytes + B_WM))[(size_t)n * 512 + k] = __float2half(s * (1.f / 81.f));
    if (idx < ATOMS) {
        float t = 0.f;
        for (int a = 0; a < ACTIONS; a++) t += b[a * ATOMS + idx];
        ((float*)(g_bytes + B_BM))[idx] = t * (1.f / 81.f);
    }
}

// ---------------------------------------------------------------------------
// weight transpose+convert: W (K x N fp32) -> Wt (N x Kpad fp16), zero-pad k
// ---------------------------------------------------------------------------
__global__ void convT(const float* __restrict__ W, __half* __restrict__ Wt,
                      int K, int N, int Kpad)
{
    __shared__ float tile[32][33];
    int k0 = blockIdx.y * 32, n0 = blockIdx.x * 32;
    int tx = threadIdx.x, ty = threadIdx.y;  // 32 x 8
#pragma unroll
    for (int i = 0; i < 4; i++) {
        int k = k0 + ty + 8 * i, n = n0 + tx;
        tile[ty + 8 * i][tx] = (k < K && n < N) ? W[(size_t)k * N + n] : 0.f;
    }
    __syncthreads();
#pragma unroll
    for (int i = 0; i < 4; i++) {
        int n = n0 + ty + 8 * i, k = k0 + tx;
        if (n < N && k < Kpad)
            Wt[(size_t)n * Kpad + k] = __float2half(tile[tx][ty + 8 * i]);
    }
}

__global__ void conv_state(const float* __restrict__ state)
{
    int b = blockIdx.x;
    const float* src = state + (size_t)b * STATE_SZ;
    __half* dst = (__half*)(g_bytes + B_STATEH) + (size_t)b * KPAD0;
    for (int k = threadIdx.x; k < KPAD0; k += 256)
        dst[k] = (k < STATE_SZ) ? __float2half(src[k]) : __float2half(0.f);
}

// ---------------------------------------------------------------------------
// attention kernel: one block per batch item, 128 threads (4 warps)
// ---------------------------------------------------------------------------
__device__ __forceinline__ void slot_info(int s, int& cat, int& off) {
    const int defs[9] = {16, 8, 4, 4, 4, 8, 8, 8, 8};
    int base = 59, acc = 0;
#pragma unroll
    for (int c = 0; c < 9; c++) {
        if (s < acc + defs[c]) { cat = c; off = base + 1 + (s - acc) * 4; return; }
        acc += defs[c];
        base += 1 + defs[c] * 4;
    }
    cat = 8; off = 0;
}

__global__ __launch_bounds__(128)
void attn_k(const float* __restrict__ state,
            const float* __restrict__ embW, const float* __restrict__ embB,
            const float* __restrict__ lng,  const float* __restrict__ lnb,
            const float* __restrict__ cls)
{
    int b = blockIdx.x;
    int tid = threadIdx.x;
    int lane = tid & 31, warp = tid >> 5;

    __shared__ float xs[69][128];
    __shared__ float tokf[68][8];
    __shared__ float sc[4][72];
    __shared__ int s_any;

    const float* st = state + (size_t)b * STATE_SZ;
    float presv = 0.f;
    if (tid < 68) {
        int cat, off;
        slot_info(tid, cat, off);
        float p   = st[1020 + off + 0];
        float dx  = st[1020 + off + 1];
        float dy  = st[1020 + off + 2];
        float di  = st[1020 + off + 3];
        float pp  = st[680 + off + 0];
        float pdx = st[680 + off + 1];
        float pdy = st[680 + off + 2];
        float vv  = (p > 0.5f && pp > 0.5f) ? 1.f : 0.f;
        tokf[tid][0] = dx;
        tokf[tid][1] = dy;
        tokf[tid][2] = di;
        tokf[tid][3] = (dx - pdx) * vv;
        tokf[tid][4] = (dy - pdy) * vv;
        tokf[tid][5] = (float)cat * 0.125f;
        tokf[tid][6] = p;
        presv = p;
    }
    if (tid == 127) s_any = 0;
    __syncthreads();
    if (tid < 68 && presv >= 0.5f) atomicOr(&s_any, 1);
    __syncthreads();
    int all_empty = (s_any == 0);

    const float* wsc = (const float*)(g_bytes + B_WS);
    const float* csc = (const float*)(g_bytes + B_CS);

    for (int j = warp; j < 69; j += 4) {
        float xv[4];
        if (j == 0) {
#pragma unroll
            for (int q = 0; q < 4; q++) xv[q] = cls[lane + 32 * q];
        } else {
            const float* tf = tokf[j - 1];
            float f0 = tf[0], f1 = tf[1], f2 = tf[2], f3 = tf[3], f4 = tf[4], f5 = tf[5], f6 = tf[6];
#pragma unroll
            for (int q = 0; q < 4; q++) {
                int d = lane + 32 * q;
                float e = embB[d];
                e += f0 * embW[0 * 128 + d];
                e += f1 * embW[1 * 128 + d];
                e += f2 * embW[2 * 128 + d];
                e += f3 * embW[3 * 128 + d];
                e += f4 * embW[4 * 128 + d];
                e += f5 * embW[5 * 128 + d];
                e += f6 * embW[6 * 128 + d];
                xv[q] = e;
            }
            float s = xv[0] + xv[1] + xv[2] + xv[3];
            float ss = xv[0]*xv[0] + xv[1]*xv[1] + xv[2]*xv[2] + xv[3]*xv[3];
            s = wsum(s); ss = wsum(ss);
            float mean = s * (1.f / 128.f);
            float var  = ss * (1.f / 128.f) - mean * mean;
            float inv  = rsqrtf(var + 1e-5f);
#pragma unroll
            for (int q = 0; q < 4; q++) {
                int d = lane + 32 * q;
                xv[q] = (xv[q] - mean) * inv * lng[d] + lnb[d];
            }
        }
#pragma unroll
        for (int q = 0; q < 4; q++) xs[j][lane + 32 * q] = xv[q];

        float s0 = 0, s1 = 0, s2 = 0, s3 = 0;
#pragma unroll
        for (int q = 0; q < 4; q++) {
            int d = lane + 32 * q;
            float x = xv[q];
            s0 += x * wsc[d];
            s1 += x * wsc[128 + d];
            s2 += x * wsc[256 + d];
            s3 += x * wsc[384 + d];
        }
        s0 = wsum(s0); s1 = wsum(s1); s2 = wsum(s2); s3 = wsum(s3);
        if (lane == 0) {
            bool masked = (j > 0) && (tokf[j - 1][6] < 0.5f) && !all_empty;
            sc[0][j] = masked ? -1e9f : s0 + csc[0];
            sc[1][j] = masked ? -1e9f : s1 + csc[1];
            sc[2][j] = masked ? -1e9f : s2 + csc[2];
            sc[3][j] = masked ? -1e9f : s3 + csc[3];
        }
    }
    __syncthreads();

    {
        int h = warp;
        float v0 = (lane < 69)      ? sc[h][lane]      : -1e30f;
        float v1 = (lane + 32 < 69) ? sc[h][lane + 32] : -1e30f;
        float v2 = (lane + 64 < 69) ? sc[h][lane + 64] : -1e30f;
        float m = wmax(fmaxf(fmaxf(v0, v1), v2));
        float e0 = (lane < 69)      ? expf(v0 - m) : 0.f;
        float e1 = (lane + 32 < 69) ? expf(v1 - m) : 0.f;
        float e2 = (lane + 64 < 69) ? expf(v2 - m) : 0.f;
        float s = wsum(e0 + e1 + e2);
        float inv = 1.f / s;
        if (lane < 69)      sc[h][lane]      = e0 * inv;
        if (lane + 32 < 69) sc[h][lane + 32] = e1 * inv;
        if (lane + 64 < 69) sc[h][lane + 64] = e2 * inv;
    }
    __syncthreads();

    {
        int d = tid;
        float a0 = 0, a1 = 0, a2 = 0, a3 = 0;
        for (int j = 0; j < 69; j++) {
            float x = xs[j][d];
            a0 += sc[0][j] * x;
            a1 += sc[1][j] * x;
            a2 += sc[2][j] * x;
            a3 += sc[3][j] * x;
        }
        __half* xw = (__half*)(g_bytes + B_XWH) + (size_t)b * 512;
        xw[d]       = __float2half(a0);
        xw[128 + d] = __float2half(a1);
        xw[256 + d] = __float2half(a2);
        xw[384 + d] = __float2half(a3);
    }
}

// ---------------------------------------------------------------------------
// fp16 tensor-core GEMM, ldmatrix + BK=64 2-stage cp.async. (as R8)
// ---------------------------------------------------------------------------
constexpr int GSMEM = 2 * 2 * 128 * 72 * 2;  // 73728 bytes

template <bool OUTH, int ACT, bool NGUARD>
__global__ __launch_bounds__(256, 2)
void gemm_f16(int M, int N, int K,
              const __half* __restrict__ A, int lda,
              const __half* __restrict__ Bt,
              const float* __restrict__ bias,
              void* __restrict__ Cv, int ldc)
{
    constexpr int LDS_ = 72;
    constexpr int ROWB = LDS_ * 2;
    extern __shared__ __half sm[];
    __half* Asm = sm;
    __half* Bsm = sm + 2 * 128 * LDS_;

    int tid = threadIdx.x, lane = tid & 31, warp = tid >> 5;
    int wm = (warp >> 2) * 64, wn = (warp & 3) * 32;
    int bm = blockIdx.y * 128, bn = blockIdx.x * 128;
    int g = lane >> 2, tg = lane & 3;
    int lg = lane >> 3, lr = lane & 7;

    uint32_t aBase, bBase;
    {
        uint64_t t = (uint64_t)__cvta_generic_to_shared(Asm);
        aBase = (uint32_t)t;
        t = (uint64_t)__cvta_generic_to_shared(Bsm);
        bBase = (uint32_t)t;
    }
    uint32_t aOffL = (uint32_t)((wm + (lg & 1) * 8 + lr) * ROWB + (lg >> 1) * 16);
    uint32_t bOffL = (uint32_t)((wn + (lg >> 1) * 8 + lr) * ROWB + (lg & 1) * 16);

    float acc[4][4][4];
#pragma unroll
    for (int i = 0; i < 4; i++)
#pragma unroll
        for (int j = 0; j < 4; j++)
#pragma unroll
            for (int c = 0; c < 4; c++) acc[i][j][c] = 0.f;

    auto issue = [&](int t, int s) {
        int k0 = t * 64;
#pragma unroll
        for (int i = 0; i < 4; i++) {
            int q = tid + 256 * i;
            int r = q >> 3, j = q & 7;
            const __half* src = A + (size_t)(bm + r) * lda + k0 + j * 8;
            uint32_t dst = (uint32_t)__cvta_generic_to_shared(
                Asm + ((size_t)s * 128 + r) * LDS_ + j * 8);
            asm volatile("cp.async.cg.shared.global [%0], [%1], 16;\n"
                         :: "r"(dst), "l"(src));
        }
#pragma unroll
        for (int i = 0; i < 4; i++) {
            int q = tid + 256 * i;
            int r = q >> 3, j = q & 7;
            int gn = bn + r;
            uint32_t dst = (uint32_t)__cvta_generic_to_shared(
                Bsm + ((size_t)s * 128 + r) * LDS_ + j * 8);
            if (NGUARD) {
                int cn = gn < N ? gn : N - 1;
                const __half* src = Bt + (size_t)cn * K + k0 + j * 8;
                int sz = gn < N ? 16 : 0;
                asm volatile("cp.async.cg.shared.global [%0], [%1], 16, %2;\n"
                             :: "r"(dst), "l"(src), "r"(sz));
            } else {
                const __half* src = Bt + (size_t)gn * K + k0 + j * 8;
                asm volatile("cp.async.cg.shared.global [%0], [%1], 16;\n"
                             :: "r"(dst), "l"(src));
            }
        }
        asm volatile("cp.async.commit_group;\n");
    };

    int NT = K / 64;
    issue(0, 0);
    asm volatile("cp.async.wait_group 0;\n");
    __syncthreads();

    for (int t = 0; t < NT; t++) {
        int s = t & 1;
        if (t + 1 < NT) issue(t + 1, s ^ 1);

        uint32_t aS = aBase + (uint32_t)(s * 128 * ROWB);
        uint32_t bS = bBase + (uint32_t)(s * 128 * ROWB);
#pragma unroll
        for (int kk = 0; kk < 4; kk++) {
            uint32_t kby = (uint32_t)(kk * 32);
            uint32_t a[4][4];
#pragma unroll
            for (int i = 0; i < 4; i++) {
                uint32_t addr = aS + aOffL + (uint32_t)(i * 16 * ROWB) + kby;
                asm volatile(
                    "ldmatrix.sync.aligned.m8n8.x4.shared.b16 {%0,%1,%2,%3}, [%4];"
                    : "=r"(a[i][0]), "=r"(a[i][1]), "=r"(a[i][2]), "=r"(a[i][3])
                    : "r"(addr));
            }
            uint32_t bf[4][2];
#pragma unroll
            for (int j2 = 0; j2 < 2; j2++) {
                uint32_t addr = bS + bOffL + (uint32_t)(j2 * 16 * ROWB) + kby;
                asm volatile(
                    "ldmatrix.sync.aligned.m8n8.x4.shared.b16 {%0,%1,%2,%3}, [%4];"
                    : "=r"(bf[2 * j2][0]), "=r"(bf[2 * j2][1]),
                      "=r"(bf[2 * j2 + 1][0]), "=r"(bf[2 * j2 + 1][1])
                    : "r"(addr));
            }
#pragma unroll
            for (int i = 0; i < 4; i++)
#pragma unroll
                for (int j = 0; j < 4; j++) {
                    asm volatile(
                        "mma.sync.aligned.m16n8k16.row.col.f32.f16.f16.f32 "
                        "{%0,%1,%2,%3},{%4,%5,%6,%7},{%8,%9},{%0,%1,%2,%3};"
                        : "+f"(acc[i][j][0]), "+f"(acc[i][j][1]),
                          "+f"(acc[i][j][2]), "+f"(acc[i][j][3])
                        : "r"(a[i][0]), "r"(a[i][1]), "r"(a[i][2]), "r"(a[i][3]),
                          "r"(bf[j][0]), "r"(bf[j][1]));
                }
        }
        if (t + 1 < NT) asm volatile("cp.async.wait_group 0;\n");
        __syncthreads();
    }

    __half* Ch = (__half*)Cv;
    float*  Cf = (float*)Cv;
#pragma unroll
    for (int i = 0; i < 4; i++) {
        int r0 = bm + wm + 16 * i + g;
#pragma unroll
        for (int j = 0; j < 4; j++) {
            int c = bn + wn + 8 * j + 2 * tg;
#pragma unroll
            for (int h = 0; h < 2; h++) {
                int r = r0 + 8 * h;
                float v0 = acc[i][j][2 * h + 0];
                float v1 = acc[i][j][2 * h + 1];
                if (NGUARD) {
                    if (c < N) {
                        float v = v0 + bias[c];
                        if (ACT == 1) v = fmaxf(v, 0.f);
                        if (OUTH) Ch[(size_t)r * ldc + c] = __float2half(v);
                        else      Cf[(size_t)r * ldc + c] = v;
                    }
                    if (c + 1 < N) {
                        float v = v1 + bias[c + 1];
                        if (ACT == 1) v = fmaxf(v, 0.f);
                        if (OUTH) Ch[(size_t)r * ldc + c + 1] = __float2half(v);
                        else      Cf[(size_t)r * ldc + c + 1] = v;
                    }
                } else {
                    float v0b = v0 + bias[c];
                    float v1b = v1 + bias[c + 1];
                    if (ACT == 1) { v0b = fmaxf(v0b, 0.f); v1b = fmaxf(v1b, 0.f); }
                    if (OUTH) {
                        *(__half2*)(Ch + (size_t)r * ldc + c) =
                            __halves2half2(__float2half(v0b), __float2half(v1b));
                    } else {
                        *(float2*)(Cf + (size_t)r * ldc + c) = make_float2(v0b, v1b);
                    }
                }
            }
        }
    }
}

// ---------------------------------------------------------------------------
// fused adv GEMM + dueling + softmax.
//   tile: 128 rows x 153 cols (= 3 whole actions); B rows guarded at 4131.
//   warp layout 2x4: warp tile 64 x 40 (cols 153..159 computed, discarded).
//   epilogue: acc -> smem (stride 165 f32, conflict-free), then per-action
//   softmax of q = adv + bias + (val - cmv), written straight to out.
// ---------------------------------------------------------------------------
constexpr int GSMEM2 = 128 * 165 * 4;  // 84480 >= mainloop smem 82944

__global__ __launch_bounds__(256)
void gemm_adv_sm(const __half* __restrict__ A, int lda,
                 const __half* __restrict__ Bt,      // 4131 x 512
                 const float* __restrict__ bias,     // 4131
                 const float* __restrict__ val,      // 8192 x 51
                 const float* __restrict__ cmv,      // 8192 x 51
                 float* __restrict__ out)            // 8192 x 4131
{
    constexpr int K = 512, NG = ADV_N;
    constexpr int LDS_ = 72, ROWB = 144;
    extern __shared__ __half sm[];
    __half* Asm = sm;                      // [2][128][72]
    __half* Bsm = sm + 2 * 128 * LDS_;     // [2][160][72]

    int tid = threadIdx.x, lane = tid & 31, warp = tid >> 5;
    int wm = (warp >> 2) * 64, wn = (warp & 3) * 40;
    int bm = blockIdx.y * 128;
    int bn = blockIdx.x * 153;
    int g = lane >> 2, tg = lane & 3;
    int lg = lane >> 3, lr = lane & 7;

    uint32_t aBase, bBase;
    {
        uint64_t t = (uint64_t)__cvta_generic_to_shared(Asm);
        aBase = (uint32_t)t;
        t = (uint64_t)__cvta_generic_to_shared(Bsm);
        bBase = (uint32_t)t;
    }
    uint32_t aOffL = (uint32_t)((wm + (lg & 1) * 8 + lr) * ROWB + (lg >> 1) * 16);
    uint32_t bOffL = (uint32_t)((wn + (lg >> 1) * 8 + lr) * ROWB + (lg & 1) * 16);
    uint32_t bOff2 = (uint32_t)((wn + 32 + lr) * ROWB + (lg & 1) * 16);

    float acc[4][5][4];
#pragma unroll
    for (int i = 0; i < 4; i++)
#pragma unroll
        for (int j = 0; j < 5; j++)
#pragma unroll
            for (int c = 0; c < 4; c++) acc[i][j][c] = 0.f;

    auto issue = [&](int t, int s) {
        int k0 = t * 64;
#pragma unroll
        for (int i = 0; i < 4; i++) {
            int q = tid + 256 * i;
            int r = q >> 3, j = q & 7;
            const __half* src = A + (size_t)(bm + r) * lda + k0 + j * 8;
            uint32_t dst = (uint32_t)__cvta_generic_to_shared(
                Asm + ((size_t)s * 128 + r) * LDS_ + j * 8);
            asm volatile("cp.async.cg.shared.global [%0], [%1], 16;\n"
                         :: "r"(dst), "l"(src));
        }
#pragma unroll
        for (int i = 0; i < 5; i++) {
            int q = tid + 256 * i;
            int r = q >> 3, j = q & 7;
            int gn = bn + r;
            int cn = gn < NG ? gn : 0;
            int sz = gn < NG ? 16 : 0;
            const __half* src = Bt + (size_t)cn * K + k0 + j * 8;
            uint32_t dst = (uint32_t)__cvta_generic_to_shared(
                Bsm + ((size_t)s * 160 + r) * LDS_ + j * 8);
            asm volatile("cp.async.cg.shared.global [%0], [%1], 16, %2;\n"
                         :: "r"(dst), "l"(src), "r"(sz));
        }
        asm volatile("cp.async.commit_group;\n");
    };

    int NT = K / 64;  // 8
    issue(0, 0);
    asm volatile("cp.async.wait_group 0;\n");
    __syncthreads();

    for (int t = 0; t < NT; t++) {
        int s = t & 1;
        if (t + 1 < NT) issue(t + 1, s ^ 1);

        uint32_t aS = aBase + (uint32_t)(s * 128 * ROWB);
        uint32_t bS = bBase + (uint32_t)(s * 160 * ROWB);
#pragma unroll
        for (int kk = 0; kk < 4; kk++) {
            uint32_t kby = (uint32_t)(kk * 32);
            uint32_t a[4][4];
#pragma unroll
            for (int i = 0; i < 4; i++) {
                uint32_t addr = aS + aOffL + (uint32_t)(i * 16 * ROWB) + kby;
                asm volatile(
                    "ldmatrix.sync.aligned.m8n8.x4.shared.b16 {%0,%1,%2,%3}, [%4];"
                    : "=r"(a[i][0]), "=r"(a[i][1]), "=r"(a[i][2]), "=r"(a[i][3])
                    : "r"(addr));
            }
            uint32_t bf[5][2];
#pragma unroll
            for (int j2 = 0; j2 < 2; j2++) {
                uint32_t addr = bS + bOffL + (uint32_t)(j2 * 16 * ROWB) + kby;
                asm volatile(
                    "ldmatrix.sync.aligned.m8n8.x4.shared.b16 {%0,%1,%2,%3}, [%4];"
                    : "=r"(bf[2 * j2][0]), "=r"(bf[2 * j2][1]),
                      "=r"(bf[2 * j2 + 1][0]), "=r"(bf[2 * j2 + 1][1])
                    : "r"(addr));
            }
            {
                uint32_t addr = bS + bOff2 + kby;
                asm volatile(
                    "ldmatrix.sync.aligned.m8n8.x2.shared.b16 {%0,%1}, [%2];"
                    : "=r"(bf[4][0]), "=r"(bf[4][1])
                    : "r"(addr));
            }
#pragma unroll
            for (int i = 0; i < 4; i++)
#pragma unroll
                for (int j = 0; j < 5; j++) {
                    asm volatile(
                        "mma.sync.aligned.m16n8k16.row.col.f32.f16.f16.f32 "
                        "{%0,%1,%2,%3},{%4,%5,%6,%7},{%8,%9},{%0,%1,%2,%3};"
                        : "+f"(acc[i][j][0]), "+f"(acc[i][j][1]),
                          "+f"(acc[i][j][2]), "+f"(acc[i][j][3])
                        : "r"(a[i][0]), "r"(a[i][1]), "r"(a[i][2]), "r"(a[i][3]),
                          "r"(bf[j][0]), "r"(bf[j][1]));
                }
        }
        if (t + 1 < NT) asm volatile("cp.async.wait_group 0;\n");
        __syncthreads();
    }

    // stage to smem (stride 165 floats), adding adv bias
    float* qs = (float*)sm;
#pragma unroll
    for (int i = 0; i < 4; i++) {
        int r0 = wm + 16 * i + g;
#pragma unroll
        for (int j = 0; j < 5; j++) {
            int cl = wn + 8 * j + 2 * tg;
            int gc = bn + cl;
            float b0 = (gc     < NG) ? bias[gc]     : 0.f;
            float b1 = (gc + 1 < NG) ? bias[gc + 1] : 0.f;
            qs[r0 * 165 + cl]           = acc[i][j][0] + b0;
            qs[r0 * 165 + cl + 1]       = acc[i][j][1] + b1;
            qs[(r0 + 8) * 165 + cl]     = acc[i][j][2] + b0;
            qs[(r0 + 8) * 165 + cl + 1] = acc[i][j][3] + b1;
        }
    }
    __syncthreads();

    // per-action softmax; warp w handles rows 16w..16w+15
    int actg = blockIdx.x * 3;
    bool v1ok = (lane + 32) < ATOMS;
    for (int rr = 0; rr < 16; rr++) {
        int r = warp * 16 + rr;
        int b = bm + r;
        float dv0 = val[(size_t)b * ATOMS + lane] - cmv[(size_t)b * ATOMS + lane];
        float dv1 = v1ok ? (val[(size_t)b * ATOMS + lane + 32] -
                            cmv[(size_t)b * ATOMS + lane + 32]) : 0.f;
#pragma unroll
        for (int act = 0; act < 3; act++) {
            float q0 = qs[r * 165 + act * 51 + lane] + dv0;
            float q1 = v1ok ? (qs[r * 165 + act * 51 + lane + 32] + dv1) : -1e30f;
            float m = wmax(fmaxf(q0, q1));
            float e0 = expf(q0 - m);
            float e1 = v1ok ? expf(q1 - m) : 0.f;
            float ssum = wsum(e0 + e1);
            float inv = 1.f / ssum;
            float* op = out + (size_t)b * ADV_N + (size_t)(actg + act) * ATOMS;
            op[lane] = e0 * inv;
            if (v1ok) op[lane + 32] = e1 * inv;
        }
    }
}

// ---------------------------------------------------------------------------
// rowwise layernorm + relu: fp32 in -> fp16 out, one block per row
// ---------------------------------------------------------------------------
__global__ void ln_relu_k(const float* __restrict__ x, __half* __restrict__ y,
                          const float* __restrict__ g, const float* __restrict__ bta,
                          int L)
{
    size_t row = blockIdx.x;
    const float* p = x + row * (size_t)L;
    __half* q = y + row * (size_t)L;
    int tid = threadIdx.x;
    float s = 0.f, ss = 0.f;
    for (int i = tid; i < L; i += 256) {
        float v = p[i];
        s += v; ss += v * v;
    }
    __shared__ float sh1[8], sh2[8];
    s = wsum(s); ss = wsum(ss);
    int w = tid >> 5, l = tid & 31;
    if (l == 0) { sh1[w] = s; sh2[w] = ss; }
    __syncthreads();
    if (w == 0) {
        float a = (l < 8) ? sh1[l] : 0.f;
        float c = (l < 8) ? sh2[l] : 0.f;
        a = wsum(a); c = wsum(c);
        if (l == 0) { sh1[0] = a; sh2[0] = c; }
    }
    __syncthreads();
    float mean = sh1[0] / (float)L;
    float var  = sh2[0] / (float)L - mean * mean;
    float inv  = rsqrtf(var + 1e-5f);
    for (int i = tid; i < L; i += 256) {
        float v = p[i];
        q[i] = __float2half(fmaxf((v - mean) * inv * g[i] + bta[i], 0.f));
    }
}

// ---------------------------------------------------------------------------
extern "C" void kernel_launch(void* const* d_in, const int* in_sizes, int n_in,
                              void* d_out, int out_size)
{
    const float* state     = (const float*)d_in[0];
    const float* embed_W   = (const float*)d_in[1];
    const float* embed_b   = (const float*)d_in[2];
    const float* ln_g      = (const float*)d_in[3];
    const float* ln_b      = (const float*)d_in[4];
    const float* cls_tok   = (const float*)d_in[5];
    const float* in_proj_W = (const float*)d_in[6];
    const float* in_proj_b = (const float*)d_in[7];
    const float* out_proj_W= (const float*)d_in[8];
    const float* out_proj_b= (const float*)d_in[9];
    const float* t0_W      = (const float*)d_in[10];
    const float* t0_b      = (const float*)d_in[11];
    const float* t0_g      = (const float*)d_in[12];
    const float* t0_beta   = (const float*)d_in[13];
    const float* t1_W      = (const float*)d_in[14];
    const float* t1_b      = (const float*)d_in[15];
    const float* t1_g      = (const float*)d_in[16];
    const float* t1_beta   = (const float*)d_in[17];
    const float* val_fc_W  = (const float*)d_in[18];
    const float* val_fc_b  = (const float*)d_in[19];
    const float* val_out_W = (const float*)d_in[20];
    const float* val_out_b = (const float*)d_in[21];
    const float* adv_fc_W  = (const float*)d_in[22];
    const float* adv_fc_b  = (const float*)d_in[23];
    const float* adv_out_W = (const float*)d_in[24];
    const float* adv_out_b = (const float*)d_in[25];
    float* out = (float*)d_out;

    unsigned char* base = nullptr;
    cudaGetSymbolAddress((void**)&base, g_bytes);
    __half* stateH = (__half*)(base + B_STATEH);
    __half* xwH    = (__half*)(base + B_XWH);
    float*  z0     = (float*)(base + B_Z0);
    __half* z0H    = (__half*)(base + B_Z0H);
    float*  h1     = (float*)(base + B_H1);
    __half* h1H    = (__half*)(base + B_H1H);
    __half* combH  = (__half*)(base + B_COMBH);
    float*  val    = (float*)(base + B_VAL);
    float*  cmv    = (float*)(base + B_CMV);
    __half* t0Wt   = (__half*)(base + B_T0W);
    __half* t1Wt   = (__half*)(base + B_T1W);
    __half* vfcWt  = (__half*)(base + B_VFCW);
    __half* afcWt  = (__half*)(base + B_AFCW);
    __half* voWt   = (__half*)(base + B_VOW);
    __half* aoWt   = (__half*)(base + B_AOW);
    __half* Mt     = (__half*)(base + B_MT);
    float*  cpool  = (float*)(base + B_CP);
    float*  fcb    = (float*)(base + B_FCB);
    __half* WmT    = (__half*)(base + B_WM);
    float*  bm     = (float*)(base + B_BM);

    cudaFuncSetAttribute(gemm_f16<true, 0, false>,
                         cudaFuncAttributeMaxDynamicSharedMemorySize, GSMEM);
    cudaFuncSetAttribute(gemm_f16<false, 0, false>,
                         cudaFuncAttributeMaxDynamicSharedMemorySize, GSMEM);
    cudaFuncSetAttribute(gemm_f16<true, 1, false>,
                         cudaFuncAttributeMaxDynamicSharedMemorySize, GSMEM);
    cudaFuncSetAttribute(gemm_f16<false, 0, true>,
                         cudaFuncAttributeMaxDynamicSharedMemorySize, GSMEM);
    cudaFuncSetAttribute(gemm_adv_sm,
                         cudaFuncAttributeMaxDynamicSharedMemorySize, GSMEM2);

    dim3 t32x8(32, 8);
    conv_state<<<BQ, 256>>>(state);
    convT<<<dim3(32, 48), t32x8>>>(t0_W, t0Wt, 1488, 1024, KPAD0);
    convT<<<dim3(32, 32), t32x8>>>(t1_W, t1Wt, 1024, 1024, 1024);
    convT<<<dim3(16, 32), t32x8>>>(val_fc_W, vfcWt, 1024, 512, 1024);
    convT<<<dim3(16, 32), t32x8>>>(adv_fc_W, afcWt, 1024, 512, 1024);
    convT<<<dim3(2, 16),  t32x8>>>(val_out_W, voWt, 512, ATOMS, 512);
    convT<<<dim3(130, 16), t32x8>>>(adv_out_W, aoWt, 512, ADV_N, 512);

    prep_small<<<1, 128>>>(cls_tok, in_proj_W, in_proj_b, out_proj_W, out_proj_b);
    prep_M<<<256, 256>>>(in_proj_W, out_proj_W);
    prep_fcb<<<4, 256>>>(val_fc_b, adv_fc_b);
    prep_wm<<<102, 256>>>(adv_out_W, adv_out_b);

    attn_k<<<BQ, 128>>>(state, embed_W, embed_b, ln_g, ln_b, cls_tok);

    // pooled (fp16) -> stateH cols 1360..1487
    gemm_f16<true, 0, false><<<dim3(1, 64), 256, GSMEM>>>(
        BQ, 128, 512, xwH, 512, Mt, cpool, stateH + 1360, KPAD0);

    // trunk 0
    gemm_f16<false, 0, false><<<dim3(8, 64), 256, GSMEM>>>(
        BQ, TRUNK_H, KPAD0, stateH, KPAD0, t0Wt, t0_b, z0, TRUNK_H);
    ln_relu_k<<<BQ, 256>>>(z0, z0H, t0_g, t0_beta, TRUNK_H);

    // trunk 1
    gemm_f16<false, 0, false><<<dim3(8, 64), 256, GSMEM>>>(
        BQ, TRUNK_H, TRUNK_H, z0H, TRUNK_H, t1Wt, t1_b, h1, TRUNK_H);
    ln_relu_k<<<BQ, 256>>>(h1, h1H, t1_g, t1_beta, TRUNK_H);

    // combined val_fc | adv_fc (relu fused, fp16 out, [b][0..511]=val, [512..1023]=adv)
    gemm_f16<true, 1, false><<<dim3(8, 64), 256, GSMEM>>>(
        BQ, 1024, TRUNK_H, h1H, TRUNK_H, vfcWt, fcb, combH, 1024);

    // val head (N=51) and mean-adv head (N=51)
    gemm_f16<false, 0, true><<<dim3(1, 64), 256, GSMEM>>>(
        BQ, ATOMS, HALF_H, combH, 1024, voWt, val_out_b, val, ATOMS);
    gemm_f16<false, 0, true><<<dim3(1, 64), 256, GSMEM>>>(
        BQ, ATOMS, HALF_H, combH + 512, 1024, WmT, bm, cmv, ATOMS);

    // fused adv GEMM + dueling + softmax -> out
    gemm_adv_sm<<<dim3(27, 64), 256, GSMEM2>>>(
        combH + 512, 1024, aoWt, adv_out_b, val, cmv, out);

    (void)in_sizes; (void)n_in; (void)out_size;
}

// round 11
// speedup vs baseline: 1.7005x; 1.0018x over previous
#include <cuda_runtime.h>
#include <cuda_fp16.h>
#include <math.h>
#include <stdint.h>

// ---------------------------------------------------------------------------
// RainbowNet fused inference — fp16 warp-MMA + ldmatrix, BK=64 2-stage,
// fused dueling-softmax adv GEMM; R10: conv_state merged into attn_k,
// val+cmv heads merged (block-diagonal weight), launch order tuned so ncu
// samples attn_k.
// ---------------------------------------------------------------------------

constexpr int BQ       = 8192;
constexpr int STATE_SZ = 1360;
constexpr int KPAD0    = 1536;   // 1488 padded to multiple of 64
constexpr int TRUNK_H  = 1024;
constexpr int HALF_H   = 512;
constexpr int ATOMS    = 51;
constexpr int ACTIONS  = 81;
constexpr int ADV_N    = ACTIONS * ATOMS;  // 4131
constexpr int VC_N     = 102;              // [val(51) | cmv(51)]

constexpr size_t al256(size_t x) { return (x + 255) & ~(size_t)255; }
constexpr size_t B_STATEH = 0;
constexpr size_t B_XWH   = al256(B_STATEH + (size_t)BQ * KPAD0 * 2);
constexpr size_t B_Z0    = al256(B_XWH   + (size_t)BQ * 512 * 2);
constexpr size_t B_Z0H   = al256(B_Z0    + (size_t)BQ * 1024 * 4);
constexpr size_t B_H1    = al256(B_Z0H   + (size_t)BQ * 1024 * 2);
constexpr size_t B_H1H   = al256(B_H1    + (size_t)BQ * 1024 * 4);
constexpr size_t B_COMBH = al256(B_H1H   + (size_t)BQ * 1024 * 2);  // 8192x1024 h
constexpr size_t B_VC    = al256(B_COMBH + (size_t)BQ * 1024 * 2);  // 8192x102 f
constexpr size_t B_T0W   = al256(B_VC    + (size_t)BQ * VC_N * 4);
constexpr size_t B_T1W   = al256(B_T0W   + (size_t)1024 * KPAD0 * 2);
constexpr size_t B_VFCW  = al256(B_T1W   + (size_t)1024 * 1024 * 2);
constexpr size_t B_AFCW  = al256(B_VFCW  + (size_t)512 * 1024 * 2);  // contiguous
constexpr size_t B_AOW   = al256(B_AFCW  + (size_t)512 * 1024 * 2);
constexpr size_t B_MT    = al256(B_AOW   + (size_t)ADV_N * 512 * 2);
constexpr size_t B_QVEC  = al256(B_MT    + (size_t)128 * 512 * 2);
constexpr size_t B_WS    = al256(B_QVEC  + 512);
constexpr size_t B_CS    = al256(B_WS    + 2048);
constexpr size_t B_CP    = al256(B_CS    + 64);
constexpr size_t B_FCB   = al256(B_CP    + 512);                      // 1024 f
constexpr size_t B_VOC   = al256(B_FCB   + 4096);                     // 102x1024 h
constexpr size_t B_VCB   = al256(B_VOC   + (size_t)VC_N * 1024 * 2);  // 102 f
constexpr size_t B_TOTAL = al256(B_VCB   + 512);

__device__ __align__(256) unsigned char g_bytes[B_TOTAL];

__device__ __forceinline__ float wsum(float v) {
#pragma unroll
    for (int o = 16; o > 0; o >>= 1) v += __shfl_xor_sync(0xffffffffu, v, o);
    return v;
}
__device__ __forceinline__ float wmax(float v) {
#pragma unroll
    for (int o = 16; o > 0; o >>= 1) v = fmaxf(v, __shfl_xor_sync(0xffffffffu, v, o));
    return v;
}

// ---------------------------------------------------------------------------
// prep kernels
// ---------------------------------------------------------------------------
__global__ void prep_small(const float* __restrict__ cls,
                           const float* __restrict__ ipW,
                           const float* __restrict__ ipB,
                           const float* __restrict__ opW,
                           const float* __restrict__ opB)
{
    int tid = threadIdx.x;
    float* qvec   = (float*)(g_bytes + B_QVEC);
    float* wscore = (float*)(g_bytes + B_WS);
    float* cscore = (float*)(g_bytes + B_CS);
    float* cpool  = (float*)(g_bytes + B_CP);

    {
        float q = ipB[tid];
        const float* wrow = ipW + (size_t)tid * 128;
        for (int d = 0; d < 128; d++) q += cls[d] * wrow[d];
        qvec[tid] = q;
    }
    __syncthreads();

    const float rs = 0.17677669529663687f;
    for (int idx = tid; idx < 512; idx += 128) {
        int h = idx >> 7, d = idx & 127;
        float s = 0.f;
        for (int e = 0; e < 32; e++)
            s += qvec[h * 32 + e] * ipW[(size_t)(128 + h * 32 + e) * 128 + d];
        wscore[idx] = s * rs;
    }
    if (tid < 4) {
        float s = 0.f;
        for (int e = 0; e < 32; e++)
            s += qvec[tid * 32 + e] * ipB[128 + tid * 32 + e];
        cscore[tid] = s * rs;
    }
    {
        float c = opB[tid];
        const float* orow = opW + (size_t)tid * 128;
        for (int e = 0; e < 128; e++) c += orow[e] * ipB[256 + e];
        cpool[tid] = c;
    }
}

__global__ void prep_M(const float* __restrict__ ipW, const float* __restrict__ opW)
{
    int idx = blockIdx.x * blockDim.x + threadIdx.x;
    if (idx >= 512 * 128) return;
    int d = idx & 127;
    int k = idx >> 7;
    int h = k >> 7;
    int c = k & 127;
    float s = 0.f;
    for (int e = 0; e < 32; e++)
        s += ipW[(size_t)(256 + h * 32 + e) * 128 + c] * opW[(size_t)d * 128 + h * 32 + e];
    ((__half*)(g_bytes + B_MT))[(size_t)d * 512 + k] = __float2half(s);
}

// concat bias for combined fc GEMM
__global__ void prep_fcb(const float* __restrict__ vb, const float* __restrict__ ab)
{
    int i = blockIdx.x * 256 + threadIdx.x;
    float* fcb = (float*)(g_bytes + B_FCB);
    if (i < 512) fcb[i] = vb[i];
    else if (i < 1024) fcb[i] = ab[i - 512];
}

// block-diagonal merged head weight (N-major, Kpad=1024):
//   n in [0,51):   voc[n][k] = (k<512)  ? val_out_W[k][n]              : 0
//   n in [51,102): voc[n][k] = (k>=512) ? mean_a adv_out_W[k-512][a,n-51] : 0
// bias: vcb[n<51]=val_out_b[n]; vcb[51+m]=mean_a adv_out_b[a,m]
__global__ void prep_voc(const float* __restrict__ voW, const float* __restrict__ vob,
                         const float* __restrict__ aoW, const float* __restrict__ aob)
{
    int idx = blockIdx.x * 256 + threadIdx.x;
    __half* voc = (__half*)(g_bytes + B_VOC);
    float*  vcb = (float*)(g_bytes + B_VCB);
    if (idx < VC_N * 1024) {
        int n = idx / 1024, k = idx % 1024;
        float v = 0.f;
        if (n < ATOMS) {
            if (k < 512) v = voW[(size_t)k * ATOMS + n];
        } else {
            if (k >= 512) {
                int m = n - ATOMS, kk = k - 512;
                float s = 0.f;
                for (int a = 0; a < ACTIONS; a++)
                    s += aoW[(size_t)kk * ADV_N + a * ATOMS + m];
                v = s * (1.f / 81.f);
            }
        }
        voc[(size_t)n * 1024 + k] = __float2half(v);
    }
    if (idx < ATOMS) {
        vcb[idx] = vob[idx];
        float t = 0.f;
        for (int a = 0; a < ACTIONS; a++) t += aob[a * ATOMS + idx];
        vcb[ATOMS + idx] = t * (1.f / 81.f);
    }
}

// ---------------------------------------------------------------------------
// weight transpose+convert: W (K x N fp32) -> Wt (N x Kpad fp16), zero-pad k
// ---------------------------------------------------------------------------
__global__ void convT(const float* __restrict__ W, __half* __restrict__ Wt,
                      int K, int N, int Kpad)
{
    __shared__ float tile[32][33];
    int k0 = blockIdx.y * 32, n0 = blockIdx.x * 32;
    int tx = threadIdx.x, ty = threadIdx.y;  // 32 x 8
#pragma unroll
    for (int i = 0; i < 4; i++) {
        int k = k0 + ty + 8 * i, n = n0 + tx;
        tile[ty + 8 * i][tx] = (k < K && n < N) ? W[(size_t)k * N + n] : 0.f;
    }
    __syncthreads();
#pragma unroll
    for (int i = 0; i < 4; i++) {
        int n = n0 + ty + 8 * i, k = k0 + tx;
        if (n < N && k < Kpad)
            Wt[(size_t)n * Kpad + k] = __float2half(tile[tx][ty + 8 * i]);
    }
}

// ---------------------------------------------------------------------------
// attention kernel: one block per batch item, 128 threads (4 warps).
// Also converts the full state row to fp16 (merged conv_state).
// ---------------------------------------------------------------------------
__device__ __forceinline__ void slot_info(int s, int& cat, int& off) {
    const int defs[9] = {16, 8, 4, 4, 4, 8, 8, 8, 8};
    int base = 59, acc = 0;
#pragma unroll
    for (int c = 0; c < 9; c++) {
        if (s < acc + defs[c]) { cat = c; off = base + 1 + (s - acc) * 4; return; }
        acc += defs[c];
        base += 1 + defs[c] * 4;
    }
    cat = 8; off = 0;
}

__global__ __launch_bounds__(128)
void attn_k(const float* __restrict__ state,
            const float* __restrict__ embW, const float* __restrict__ embB,
            const float* __restrict__ lng,  const float* __restrict__ lnb,
            const float* __restrict__ cls)
{
    int b = blockIdx.x;
    int tid = threadIdx.x;
    int lane = tid & 31, warp = tid >> 5;

    __shared__ float xs[69][128];
    __shared__ float tokf[68][8];
    __shared__ float sc[4][72];
    __shared__ int s_any;

    const float* st = state + (size_t)b * STATE_SZ;

    // merged conv_state: full-row fp16 convert + zero pad
    {
        __half* dst = (__half*)(g_bytes + B_STATEH) + (size_t)b * KPAD0;
        for (int k = tid; k < KPAD0; k += 128)
            dst[k] = (k < STATE_SZ) ? __float2half(st[k]) : __float2half(0.f);
    }

    float presv = 0.f;
    if (tid < 68) {
        int cat, off;
        slot_info(tid, cat, off);
        float p   = st[1020 + off + 0];
        float dx  = st[1020 + off + 1];
        float dy  = st[1020 + off + 2];
        float di  = st[1020 + off + 3];
        float pp  = st[680 + off + 0];
        float pdx = st[680 + off + 1];
        float pdy = st[680 + off + 2];
        float vv  = (p > 0.5f && pp > 0.5f) ? 1.f : 0.f;
        tokf[tid][0] = dx;
        tokf[tid][1] = dy;
        tokf[tid][2] = di;
        tokf[tid][3] = (dx - pdx) * vv;
        tokf[tid][4] = (dy - pdy) * vv;
        tokf[tid][5] = (float)cat * 0.125f;
        tokf[tid][6] = p;
        presv = p;
    }
    if (tid == 127) s_any = 0;
    __syncthreads();
    if (tid < 68 && presv >= 0.5f) atomicOr(&s_any, 1);
    __syncthreads();
    int all_empty = (s_any == 0);

    const float* wsc = (const float*)(g_bytes + B_WS);
    const float* csc = (const float*)(g_bytes + B_CS);

    for (int j = warp; j < 69; j += 4) {
        float xv[4];
        if (j == 0) {
#pragma unroll
            for (int q = 0; q < 4; q++) xv[q] = cls[lane + 32 * q];
        } else {
            const float* tf = tokf[j - 1];
            float f0 = tf[0], f1 = tf[1], f2 = tf[2], f3 = tf[3], f4 = tf[4], f5 = tf[5], f6 = tf[6];
#pragma unroll
            for (int q = 0; q < 4; q++) {
                int d = lane + 32 * q;
                float e = embB[d];
                e += f0 * embW[0 * 128 + d];
                e += f1 * embW[1 * 128 + d];
                e += f2 * embW[2 * 128 + d];
                e += f3 * embW[3 * 128 + d];
                e += f4 * embW[4 * 128 + d];
                e += f5 * embW[5 * 128 + d];
                e += f6 * embW[6 * 128 + d];
                xv[q] = e;
            }
            float s = xv[0] + xv[1] + xv[2] + xv[3];
            float ss = xv[0]*xv[0] + xv[1]*xv[1] + xv[2]*xv[2] + xv[3]*xv[3];
            s = wsum(s); ss = wsum(ss);
            float mean = s * (1.f / 128.f);
            float var  = ss * (1.f / 128.f) - mean * mean;
            float inv  = rsqrtf(var + 1e-5f);
#pragma unroll
            for (int q = 0; q < 4; q++) {
                int d = lane + 32 * q;
                xv[q] = (xv[q] - mean) * inv * lng[d] + lnb[d];
            }
        }
#pragma unroll
        for (int q = 0; q < 4; q++) xs[j][lane + 32 * q] = xv[q];

        float s0 = 0, s1 = 0, s2 = 0, s3 = 0;
#pragma unroll
        for (int q = 0; q < 4; q++) {
            int d = lane + 32 * q;
            float x = xv[q];
            s0 += x * wsc[d];
            s1 += x * wsc[128 + d];
            s2 += x * wsc[256 + d];
            s3 += x * wsc[384 + d];
        }
        s0 = wsum(s0); s1 = wsum(s1); s2 = wsum(s2); s3 = wsum(s3);
        if (lane == 0) {
            bool masked = (j > 0) && (tokf[j - 1][6] < 0.5f) && !all_empty;
            sc[0][j] = masked ? -1e9f : s0 + csc[0];
            sc[1][j] = masked ? -1e9f : s1 + csc[1];
            sc[2][j] = masked ? -1e9f : s2 + csc[2];
            sc[3][j] = masked ? -1e9f : s3 + csc[3];
        }
    }
    __syncthreads();

    {
        int h = warp;
        float v0 = (lane < 69)      ? sc[h][lane]      : -1e30f;
        float v1 = (lane + 32 < 69) ? sc[h][lane + 32] : -1e30f;
        float v2 = (lane + 64 < 69) ? sc[h][lane + 64] : -1e30f;
        float m = wmax(fmaxf(fmaxf(v0, v1), v2));
        float e0 = (lane < 69)      ? expf(v0 - m) : 0.f;
        float e1 = (lane + 32 < 69) ? expf(v1 - m) : 0.f;
        float e2 = (lane + 64 < 69) ? expf(v2 - m) : 0.f;
        float s = wsum(e0 + e1 + e2);
        float inv = 1.f / s;
        if (lane < 69)      sc[h][lane]      = e0 * inv;
        if (lane + 32 < 69) sc[h][lane + 32] = e1 * inv;
        if (lane + 64 < 69) sc[h][lane + 64] = e2 * inv;
    }
    __syncthreads();

    {
        int d = tid;
        float a0 = 0, a1 = 0, a2 = 0, a3 = 0;
        for (int j = 0; j < 69; j++) {
            float x = xs[j][d];
            a0 += sc[0][j] * x;
            a1 += sc[1][j] * x;
            a2 += sc[2][j] * x;
            a3 += sc[3][j] * x;
        }
        __half* xw = (__half*)(g_bytes + B_XWH) + (size_t)b * 512;
        xw[d]       = __float2half(a0);
        xw[128 + d] = __float2half(a1);
        xw[256 + d] = __float2half(a2);
        xw[384 + d] = __float2half(a3);
    }
}

// ---------------------------------------------------------------------------
// fp16 tensor-core GEMM, ldmatrix + BK=64 2-stage cp.async.
// ---------------------------------------------------------------------------
constexpr int GSMEM = 2 * 2 * 128 * 72 * 2;  // 73728 bytes

template <bool OUTH, int ACT, bool NGUARD>
__global__ __launch_bounds__(256, 2)
void gemm_f16(int M, int N, int K,
              const __half* __restrict__ A, int lda,
              const __half* __restrict__ Bt,
              const float* __restrict__ bias,
              void* __restrict__ Cv, int ldc)
{
    constexpr int LDS_ = 72;
    constexpr int ROWB = LDS_ * 2;
    extern __shared__ __half sm[];
    __half* Asm = sm;
    __half* Bsm = sm + 2 * 128 * LDS_;

    int tid = threadIdx.x, lane = tid & 31, warp = tid >> 5;
    int wm = (warp >> 2) * 64, wn = (warp & 3) * 32;
    int bm = blockIdx.y * 128, bn = blockIdx.x * 128;
    int g = lane >> 2, tg = lane & 3;
    int lg = lane >> 3, lr = lane & 7;

    uint32_t aBase, bBase;
    {
        uint64_t t = (uint64_t)__cvta_generic_to_shared(Asm);
        aBase = (uint32_t)t;
        t = (uint64_t)__cvta_generic_to_shared(Bsm);
        bBase = (uint32_t)t;
    }
    uint32_t aOffL = (uint32_t)((wm + (lg & 1) * 8 + lr) * ROWB + (lg >> 1) * 16);
    uint32_t bOffL = (uint32_t)((wn + (lg >> 1) * 8 + lr) * ROWB + (lg & 1) * 16);

    float acc[4][4][4];
#pragma unroll
    for (int i = 0; i < 4; i++)
#pragma unroll
        for (int j = 0; j < 4; j++)
#pragma unroll
            for (int c = 0; c < 4; c++) acc[i][j][c] = 0.f;

    auto issue = [&](int t, int s) {
        int k0 = t * 64;
#pragma unroll
        for (int i = 0; i < 4; i++) {
            int q = tid + 256 * i;
            int r = q >> 3, j = q & 7;
            const __half* src = A + (size_t)(bm + r) * lda + k0 + j * 8;
            uint32_t dst = (uint32_t)__cvta_generic_to_shared(
                Asm + ((size_t)s * 128 + r) * LDS_ + j * 8);
            asm volatile("cp.async.cg.shared.global [%0], [%1], 16;\n"
                         :: "r"(dst), "l"(src));
        }
#pragma unroll
        for (int i = 0; i < 4; i++) {
            int q = tid + 256 * i;
            int r = q >> 3, j = q & 7;
            int gn = bn + r;
            uint32_t dst = (uint32_t)__cvta_generic_to_shared(
                Bsm + ((size_t)s * 128 + r) * LDS_ + j * 8);
            if (NGUARD) {
                int cn = gn < N ? gn : N - 1;
                const __half* src = Bt + (size_t)cn * K + k0 + j * 8;
                int sz = gn < N ? 16 : 0;
                asm volatile("cp.async.cg.shared.global [%0], [%1], 16, %2;\n"
                             :: "r"(dst), "l"(src), "r"(sz));
            } else {
                const __half* src = Bt + (size_t)gn * K + k0 + j * 8;
                asm volatile("cp.async.cg.shared.global [%0], [%1], 16;\n"
                             :: "r"(dst), "l"(src));
            }
        }
        asm volatile("cp.async.commit_group;\n");
    };

    int NT = K / 64;
    issue(0, 0);
    asm volatile("cp.async.wait_group 0;\n");
    __syncthreads();

    for (int t = 0; t < NT; t++) {
        int s = t & 1;
        if (t + 1 < NT) issue(t + 1, s ^ 1);

        uint32_t aS = aBase + (uint32_t)(s * 128 * ROWB);
        uint32_t bS = bBase + (uint32_t)(s * 128 * ROWB);
#pragma unroll
        for (int kk = 0; kk < 4; kk++) {
            uint32_t kby = (uint32_t)(kk * 32);
            uint32_t a[4][4];
#pragma unroll
            for (int i = 0; i < 4; i++) {
                uint32_t addr = aS + aOffL + (uint32_t)(i * 16 * ROWB) + kby;
                asm volatile(
                    "ldmatrix.sync.aligned.m8n8.x4.shared.b16 {%0,%1,%2,%3}, [%4];"
                    : "=r"(a[i][0]), "=r"(a[i][1]), "=r"(a[i][2]), "=r"(a[i][3])
                    : "r"(addr));
            }
            uint32_t bf[4][2];
#pragma unroll
            for (int j2 = 0; j2 < 2; j2++) {
                uint32_t addr = bS + bOffL + (uint32_t)(j2 * 16 * ROWB) + kby;
                asm volatile(
                    "ldmatrix.sync.aligned.m8n8.x4.shared.b16 {%0,%1,%2,%3}, [%4];"
                    : "=r"(bf[2 * j2][0]), "=r"(bf[2 * j2][1]),
                      "=r"(bf[2 * j2 + 1][0]), "=r"(bf[2 * j2 + 1][1])
                    : "r"(addr));
            }
#pragma unroll
            for (int i = 0; i < 4; i++)
#pragma unroll
                for (int j = 0; j < 4; j++) {
                    asm volatile(
                        "mma.sync.aligned.m16n8k16.row.col.f32.f16.f16.f32 "
                        "{%0,%1,%2,%3},{%4,%5,%6,%7},{%8,%9},{%0,%1,%2,%3};"
                        : "+f"(acc[i][j][0]), "+f"(acc[i][j][1]),
                          "+f"(acc[i][j][2]), "+f"(acc[i][j][3])
                        : "r"(a[i][0]), "r"(a[i][1]), "r"(a[i][2]), "r"(a[i][3]),
                          "r"(bf[j][0]), "r"(bf[j][1]));
                }
        }
        if (t + 1 < NT) asm volatile("cp.async.wait_group 0;\n");
        __syncthreads();
    }

    __half* Ch = (__half*)Cv;
    float*  Cf = (float*)Cv;
#pragma unroll
    for (int i = 0; i < 4; i++) {
        int r0 = bm + wm + 16 * i + g;
#pragma unroll
        for (int j = 0; j < 4; j++) {
            int c = bn + wn + 8 * j + 2 * tg;
#pragma unroll
            for (int h = 0; h < 2; h++) {
                int r = r0 + 8 * h;
                float v0 = acc[i][j][2 * h + 0];
                float v1 = acc[i][j][2 * h + 1];
                if (NGUARD) {
                    if (c < N) {
                        float v = v0 + bias[c];
                        if (ACT == 1) v = fmaxf(v, 0.f);
                        if (OUTH) Ch[(size_t)r * ldc + c] = __float2half(v);
                        else      Cf[(size_t)r * ldc + c] = v;
                    }
                    if (c + 1 < N) {
                        float v = v1 + bias[c + 1];
                        if (ACT == 1) v = fmaxf(v, 0.f);
                        if (OUTH) Ch[(size_t)r * ldc + c + 1] = __float2half(v);
                        else      Cf[(size_t)r * ldc + c + 1] = v;
                    }
                } else {
                    float v0b = v0 + bias[c];
                    float v1b = v1 + bias[c + 1];
                    if (ACT == 1) { v0b = fmaxf(v0b, 0.f); v1b = fmaxf(v1b, 0.f); }
                    if (OUTH) {
                        *(__half2*)(Ch + (size_t)r * ldc + c) =
                            __halves2half2(__float2half(v0b), __float2half(v1b));
                    } else {
                        *(float2*)(Cf + (size_t)r * ldc + c) = make_float2(v0b, v1b);
                    }
                }
            }
        }
    }
}

// ---------------------------------------------------------------------------
// fused adv GEMM + dueling + softmax (as R9, vc = [val|cmv] rows of 102)
// ---------------------------------------------------------------------------
constexpr int GSMEM2 = 128 * 165 * 4;  // 84480 >= mainloop smem 82944

__global__ __launch_bounds__(256)
void gemm_adv_sm(const __half* __restrict__ A, int lda,
                 const __half* __restrict__ Bt,      // 4131 x 512
                 const float* __restrict__ bias,     // 4131
                 const float* __restrict__ vc,       // 8192 x 102 [val|cmv]
                 float* __restrict__ out)            // 8192 x 4131
{
    constexpr int K = 512, NG = ADV_N;
    constexpr int LDS_ = 72, ROWB = 144;
    extern __shared__ __half sm[];
    __half* Asm = sm;                      // [2][128][72]
    __half* Bsm = sm + 2 * 128 * LDS_;     // [2][160][72]

    int tid = threadIdx.x, lane = tid & 31, warp = tid >> 5;
    int wm = (warp >> 2) * 64, wn = (warp & 3) * 40;
    int bm = blockIdx.y * 128;
    int bn = blockIdx.x * 153;
    int g = lane >> 2, tg = lane & 3;
    int lg = lane >> 3, lr = lane & 7;

    uint32_t aBase, bBase;
    {
        uint64_t t = (uint64_t)__cvta_generic_to_shared(Asm);
        aBase = (uint32_t)t;
        t = (uint64_t)__cvta_generic_to_shared(Bsm);
        bBase = (uint32_t)t;
    }
    uint32_t aOffL = (uint32_t)((wm + (lg & 1) * 8 + lr) * ROWB + (lg >> 1) * 16);
    uint32_t bOffL = (uint32_t)((wn + (lg >> 1) * 8 + lr) * ROWB + (lg & 1) * 16);
    uint32_t bOff2 = (uint32_t)((wn + 32 + lr) * ROWB + (lg & 1) * 16);

    float acc[4][5][4];
#pragma unroll
    for (int i = 0; i < 4; i++)
#pragma unroll
        for (int j = 0; j < 5; j++)
#pragma unroll
            for (int c = 0; c < 4; c++) acc[i][j][c] = 0.f;

    auto issue = [&](int t, int s) {
        int k0 = t * 64;
#pragma unroll
        for (int i = 0; i < 4; i++) {
            int q = tid + 256 * i;
            int r = q >> 3, j = q & 7;
            const __half* src = A + (size_t)(bm + r) * lda + k0 + j * 8;
            uint32_t dst = (uint32_t)__cvta_generic_to_shared(
                Asm + ((size_t)s * 128 + r) * LDS_ + j * 8);
            asm volatile("cp.async.cg.shared.global [%0], [%1], 16;\n"
                         :: "r"(dst), "l"(src));
        }
#pragma unroll
        for (int i = 0; i < 5; i++) {
            int q = tid + 256 * i;
            int r = q >> 3, j = q & 7;
            int gn = bn + r;
            int cn = gn < NG ? gn : 0;
            int sz = gn < NG ? 16 : 0;
            const __half* src = Bt + (size_t)cn * K + k0 + j * 8;
            uint32_t dst = (uint32_t)__cvta_generic_to_shared(
                Bsm + ((size_t)s * 160 + r) * LDS_ + j * 8);
            asm volatile("cp.async.cg.shared.global [%0], [%1], 16, %2;\n"
                         :: "r"(dst), "l"(src), "r"(sz));
        }
        asm volatile("cp.async.commit_group;\n");
    };

    int NT = K / 64;  // 8
    issue(0, 0);
    asm volatile("cp.async.wait_group 0;\n");
    __syncthreads();

    for (int t = 0; t < NT; t++) {
        int s = t & 1;
        if (t + 1 < NT) issue(t + 1, s ^ 1);

        uint32_t aS = aBase + (uint32_t)(s * 128 * ROWB);
        uint32_t bS = bBase + (uint32_t)(s * 160 * ROWB);
#pragma unroll
        for (int kk = 0; kk < 4; kk++) {
            uint32_t kby = (uint32_t)(kk * 32);
            uint32_t a[4][4];
#pragma unroll
            for (int i = 0; i < 4; i++) {
                uint32_t addr = aS + aOffL + (uint32_t)(i * 16 * ROWB) + kby;
                asm volatile(
                    "ldmatrix.sync.aligned.m8n8.x4.shared.b16 {%0,%1,%2,%3}, [%4];"
                    : "=r"(a[i][0]), "=r"(a[i][1]), "=r"(a[i][2]), "=r"(a[i][3])
                    : "r"(addr));
            }
            uint32_t bf[5][2];
#pragma unroll
            for (int j2 = 0; j2 < 2; j2++) {
                uint32_t addr = bS + bOffL + (uint32_t)(j2 * 16 * ROWB) + kby;
                asm volatile(
                    "ldmatrix.sync.aligned.m8n8.x4.shared.b16 {%0,%1,%2,%3}, [%4];"
                    : "=r"(bf[2 * j2][0]), "=r"(bf[2 * j2][1]),
                      "=r"(bf[2 * j2 + 1][0]), "=r"(bf[2 * j2 + 1][1])
                    : "r"(addr));
            }
            {
                uint32_t addr = bS + bOff2 + kby;
                asm volatile(
                    "ldmatrix.sync.aligned.m8n8.x2.shared.b16 {%0,%1}, [%2];"
                    : "=r"(bf[4][0]), "=r"(bf[4][1])
                    : "r"(addr));
            }
#pragma unroll
            for (int i = 0; i < 4; i++)
#pragma unroll
                for (int j = 0; j < 5; j++) {
                    asm volatile(
                        "mma.sync.aligned.m16n8k16.row.col.f32.f16.f16.f32 "
                        "{%0,%1,%2,%3},{%4,%5,%6,%7},{%8,%9},{%0,%1,%2,%3};"
                        : "+f"(acc[i][j][0]), "+f"(acc[i][j][1]),
                          "+f"(acc[i][j][2]), "+f"(acc[i][j][3])
                        : "r"(a[i][0]), "r"(a[i][1]), "r"(a[i][2]), "r"(a[i][3]),
                          "r"(bf[j][0]), "r"(bf[j][1]));
                }
        }
        if (t + 1 < NT) asm volatile("cp.async.wait_group 0;\n");
        __syncthreads();
    }

    // stage to smem (stride 165 floats), adding adv bias
    float* qs = (float*)sm;
#pragma unroll
    for (int i = 0; i < 4; i++) {
        int r0 = wm + 16 * i + g;
#pragma unroll
        for (int j = 0; j < 5; j++) {
            int cl = wn + 8 * j + 2 * tg;
            int gc = bn + cl;
            float b0 = (gc     < NG) ? bias[gc]     : 0.f;
            float b1 = (gc + 1 < NG) ? bias[gc + 1] : 0.f;
            qs[r0 * 165 + cl]           = acc[i][j][0] + b0;
            qs[r0 * 165 + cl + 1]       = acc[i][j][1] + b1;
            qs[(r0 + 8) * 165 + cl]     = acc[i][j][2] + b0;
            qs[(r0 + 8) * 165 + cl + 1] = acc[i][j][3] + b1;
        }
    }
    __syncthreads();

    int actg = blockIdx.x * 3;
    bool v1ok = (lane + 32) < ATOMS;
    for (int rr = 0; rr < 16; rr++) {
        int r = warp * 16 + rr;
        int b = bm + r;
        const float* vcr = vc + (size_t)b * VC_N;
        float dv0 = vcr[lane] - vcr[ATOMS + lane];
        float dv1 = v1ok ? (vcr[lane + 32] - vcr[ATOMS + lane + 32]) : 0.f;
#pragma unroll
        for (int act = 0; act < 3; act++) {
            float q0 = qs[r * 165 + act * 51 + lane] + dv0;
            float q1 = v1ok ? (qs[r * 165 + act * 51 + lane + 32] + dv1) : -1e30f;
            float m = wmax(fmaxf(q0, q1));
            float e0 = expf(q0 - m);
            float e1 = v1ok ? expf(q1 - m) : 0.f;
            float ssum = wsum(e0 + e1);
            float inv = 1.f / ssum;
            float* op = out + (size_t)b * ADV_N + (size_t)(actg + act) * ATOMS;
            op[lane] = e0 * inv;
            if (v1ok) op[lane + 32] = e1 * inv;
        }
    }
}

// ---------------------------------------------------------------------------
// rowwise layernorm + relu: fp32 in -> fp16 out, one block per row
// ---------------------------------------------------------------------------
__global__ void ln_relu_k(const float* __restrict__ x, __half* __restrict__ y,
                          const float* __restrict__ g, const float* __restrict__ bta,
                          int L)
{
    size_t row = blockIdx.x;
    const float* p = x + row * (size_t)L;
    __half* q = y + row * (size_t)L;
    int tid = threadIdx.x;
    float s = 0.f, ss = 0.f;
    for (int i = tid; i < L; i += 256) {
        float v = p[i];
        s += v; ss += v * v;
    }
    __shared__ float sh1[8], sh2[8];
    s = wsum(s); ss = wsum(ss);
    int w = tid >> 5, l = tid & 31;
    if (l == 0) { sh1[w] = s; sh2[w] = ss; }
    __syncthreads();
    if (w == 0) {
        float a = (l < 8) ? sh1[l] : 0.f;
        float c = (l < 8) ? sh2[l] : 0.f;
        a = wsum(a); c = wsum(c);
        if (l == 0) { sh1[0] = a; sh2[0] = c; }
    }
    __syncthreads();
    float mean = sh1[0] / (float)L;
    float var  = sh2[0] / (float)L - mean * mean;
    float inv  = rsqrtf(var + 1e-5f);
    for (int i = tid; i < L; i += 256) {
        float v = p[i];
        q[i] = __float2half(fmaxf((v - mean) * inv * g[i] + bta[i], 0.f));
    }
}

// ---------------------------------------------------------------------------
extern "C" void kernel_launch(void* const* d_in, const int* in_sizes, int n_in,
                              void* d_out, int out_size)
{
    const float* state     = (const float*)d_in[0];
    const float* embed_W   = (const float*)d_in[1];
    const float* embed_b   = (const float*)d_in[2];
    const float* ln_g      = (const float*)d_in[3];
    const float* ln_b      = (const float*)d_in[4];
    const float* cls_tok   = (const float*)d_in[5];
    const float* in_proj_W = (const float*)d_in[6];
    const float* in_proj_b = (const float*)d_in[7];
    const float* out_proj_W= (const float*)d_in[8];
    const float* out_proj_b= (const float*)d_in[9];
    const float* t0_W      = (const float*)d_in[10];
    const float* t0_b      = (const float*)d_in[11];
    const float* t0_g      = (const float*)d_in[12];
    const float* t0_beta   = (const float*)d_in[13];
    const float* t1_W      = (const float*)d_in[14];
    const float* t1_b      = (const float*)d_in[15];
    const float* t1_g      = (const float*)d_in[16];
    const float* t1_beta   = (const float*)d_in[17];
    const float* val_fc_W  = (const float*)d_in[18];
    const float* val_fc_b  = (const float*)d_in[19];
    const float* val_out_W = (const float*)d_in[20];
    const float* val_out_b = (const float*)d_in[21];
    const float* adv_fc_W  = (const float*)d_in[22];
    const float* adv_fc_b  = (const float*)d_in[23];
    const float* adv_out_W = (const float*)d_in[24];
    const float* adv_out_b = (const float*)d_in[25];
    float* out = (float*)d_out;

    unsigned char* base = nullptr;
    cudaGetSymbolAddress((void**)&base, g_bytes);
    __half* stateH = (__half*)(base + B_STATEH);
    __half* xwH    = (__half*)(base + B_XWH);
    float*  z0     = (float*)(base + B_Z0);
    __half* z0H    = (__half*)(base + B_Z0H);
    float*  h1     = (float*)(base + B_H1);
    __half* h1H    = (__half*)(base + B_H1H);
    __half* combH  = (__half*)(base + B_COMBH);
    float*  vc     = (float*)(base + B_VC);
    __half* t0Wt   = (__half*)(base + B_T0W);
    __half* t1Wt   = (__half*)(base + B_T1W);
    __half* vfcWt  = (__half*)(base + B_VFCW);
    __half* afcWt  = (__half*)(base + B_AFCW);
    __half* aoWt   = (__half*)(base + B_AOW);
    __half* Mt     = (__half*)(base + B_MT);
    float*  cpool  = (float*)(base + B_CP);
    float*  fcb    = (float*)(base + B_FCB);
    __half* vocWt  = (__half*)(base + B_VOC);
    float*  vcb    = (float*)(base + B_VCB);

    cudaFuncSetAttribute(gemm_f16<true, 0, false>,
                         cudaFuncAttributeMaxDynamicSharedMemorySize, GSMEM);
    cudaFuncSetAttribute(gemm_f16<false, 0, false>,
                         cudaFuncAttributeMaxDynamicSharedMemorySize, GSMEM);
    cudaFuncSetAttribute(gemm_f16<true, 1, false>,
                         cudaFuncAttributeMaxDynamicSharedMemorySize, GSMEM);
    cudaFuncSetAttribute(gemm_f16<false, 0, true>,
                         cudaFuncAttributeMaxDynamicSharedMemorySize, GSMEM);
    cudaFuncSetAttribute(gemm_adv_sm,
                         cudaFuncAttributeMaxDynamicSharedMemorySize, GSMEM2);

    dim3 t32x8(32, 8);
    // launches 1-5 (prep + the two largest weight converts), then attn_k as
    // launch #6 so ncu (-s 5 -c 1) profiles it.
    prep_small<<<1, 128>>>(cls_tok, in_proj_W, in_proj_b, out_proj_W, out_proj_b);
    prep_M<<<256, 256>>>(in_proj_W, out_proj_W);
    convT<<<dim3(32, 48), t32x8>>>(t0_W, t0Wt, 1488, 1024, KPAD0);
    convT<<<dim3(32, 32), t32x8>>>(t1_W, t1Wt, 1024, 1024, 1024);
    prep_fcb<<<4, 256>>>(val_fc_b, adv_fc_b);

    attn_k<<<BQ, 128>>>(state, embed_W, embed_b, ln_g, ln_b, cls_tok);

    convT<<<dim3(16, 32), t32x8>>>(val_fc_W, vfcWt, 1024, 512, 1024);
    convT<<<dim3(16, 32), t32x8>>>(adv_fc_W, afcWt, 1024, 512, 1024);
    convT<<<dim3(130, 16), t32x8>>>(adv_out_W, aoWt, 512, ADV_N, 512);
    prep_voc<<<408, 256>>>(val_out_W, val_out_b, adv_out_W, adv_out_b);

    // pooled (fp16) -> stateH cols 1360..1487
    gemm_f16<true, 0, false><<<dim3(1, 64), 256, GSMEM>>>(
        BQ, 128, 512, xwH, 512, Mt, cpool, stateH + 1360, KPAD0);

    // trunk 0
    gemm_f16<false, 0, false><<<dim3(8, 64), 256, GSMEM>>>(
        BQ, TRUNK_H, KPAD0, stateH, KPAD0, t0Wt, t0_b, z0, TRUNK_H);
    ln_relu_k<<<BQ, 256>>>(z0, z0H, t0_g, t0_beta, TRUNK_H);

    // trunk 1
    gemm_f16<false, 0, false><<<dim3(8, 64), 256, GSMEM>>>(
        BQ, TRUNK_H, TRUNK_H, z0H, TRUNK_H, t1Wt, t1_b, h1, TRUNK_H);
    ln_relu_k<<<BQ, 256>>>(h1, h1H, t1_g, t1_beta, TRUNK_H);

    // combined val_fc | adv_fc (relu fused, fp16 out)
    gemm_f16<true, 1, false><<<dim3(8, 64), 256, GSMEM>>>(
        BQ, 1024, TRUNK_H, h1H, TRUNK_H, vfcWt, fcb, combH, 1024);

    // merged val + mean-adv heads (N=102, K=1024 block-diagonal weight)
    gemm_f16<false, 0, true><<<dim3(1, 64), 256, GSMEM>>>(
        BQ, VC_N, TRUNK_H, combH, 1024, vocWt, vcb, vc, VC_N);

    // fused adv GEMM + dueling + softmax -> out
    gemm_adv_sm<<<dim3(27, 64), 256, GSMEM2>>>(
        combH + 512, 1024, aoWt, adv_out_b, vc, out);

    (void)in_sizes; (void)n_in; (void)out_size;
}